// round 5
// baseline (speedup 1.0000x reference)
#include <cuda_runtime.h>

// ---------------------------------------------------------------------------
// BraggNN fused forward.  One sample per block, 256 threads.
// All activations live in shared memory; weights staged (pre-transposed by a
// prep kernel) into a phase-unioned shared region.
// conv2/conv3 + NLB projections + attention + wo projection use fma.rn.f32x2.
// ---------------------------------------------------------------------------

#define SLOPE 0.01f

// pre-transposed weight scratch (device globals: allocation-free)
__device__ float g_qkvT[6144];   // wtT/wpT/wgT : [c(64)][o(32)] each
__device__ float g_woT [2048];   // woT : [i(32)][c(64)]
__device__ float g_w2T [18432];  // w2T : [ci(64)][k(9)][co(32)]
__device__ float g_w3T [2304];   // w3T : [ci(32)][k(9)][co(8)]

__device__ __forceinline__ float lrelu(float v) { return v > 0.f ? v : SLOPE * v; }

// ---- packed f32x2 helpers (sm_103a) ----
__device__ __forceinline__ unsigned long long pk2(float lo, float hi) {
    unsigned long long r;
    asm("mov.b64 %0, {%1, %2};" : "=l"(r) : "f"(lo), "f"(hi));
    return r;
}
__device__ __forceinline__ unsigned long long fma2(unsigned long long a,
                                                   unsigned long long b,
                                                   unsigned long long c) {
    unsigned long long d;
    asm("fma.rn.f32x2 %0, %1, %2, %3;" : "=l"(d) : "l"(a), "l"(b), "l"(c));
    return d;
}
__device__ __forceinline__ void upk2(unsigned long long v, float& lo, float& hi) {
    asm("mov.b64 {%0, %1}, %2;" : "=f"(lo), "=f"(hi) : "l"(v));
}
__device__ __forceinline__ float sum2(unsigned long long v) {
    float lo, hi; upk2(v, lo, hi); return lo + hi;
}

__global__ void prep_kernel(const float* __restrict__ wt, const float* __restrict__ wp,
                            const float* __restrict__ wg, const float* __restrict__ wo,
                            const float* __restrict__ w2, const float* __restrict__ w3)
{
    int t = blockIdx.x * blockDim.x + threadIdx.x;
    int n = gridDim.x * blockDim.x;
    for (int i = t; i < 2048; i += n) { int o = i & 31, c = i >> 5;
        g_qkvT[i]        = wt[o * 64 + c];
        g_qkvT[2048 + i] = wp[o * 64 + c];
        g_qkvT[4096 + i] = wg[o * 64 + c]; }
    for (int i = t; i < 2048; i += n) { int c = i & 63, o = i >> 6;
        g_woT[i] = wo[c * 32 + o]; }
    for (int i = t; i < 18432; i += n) { int o = i & 31, k = (i >> 5) % 9, ci = i / 288;
        g_w2T[i] = w2[(o * 64 + ci) * 9 + k]; }
    for (int i = t; i < 2304; i += n) { int o = i & 7, k = (i >> 3) % 9, ci = i / 72;
        g_w3T[i] = w3[(o * 32 + ci) * 9 + k]; }
}

// ---- shared memory layout (float offsets) ----
constexpr int OFF_XIN = 0;            // 121 (pad 128)
constexpr int OFF_W1  = 128;          // 576
constexpr int OFF_B1  = 704;          // 64
constexpr int OFF_BT  = 768;          // 32
constexpr int OFF_BP  = 800;          // 32
constexpr int OFF_BG  = 832;          // 32
constexpr int OFF_BO  = 864;          // 64
constexpr int OFF_B2  = 928;          // 32
constexpr int OFF_B3  = 960;          // 8
constexpr int OFF_FB1 = 968;          // 64
constexpr int OFF_FB2 = 1032;         // 32
constexpr int OFF_FB3 = 1064;         // 16
constexpr int OFF_FB4 = 1080;         // 8
constexpr int OFF_FBO = 1088;         // 2 (pad 4)
constexpr int OFF_A1  = 1092;         // [64][84]  conv1/NLB activations (s padded 81->84)
constexpr int OFF_A2  = 6468;         // [32][49]  conv2 out
constexpr int OFF_A3  = 8036;         // 200 (pad 208) conv3 out flat
constexpr int OFF_H1  = 8244;         // 64
constexpr int OFF_H2  = 8308;         // 32
constexpr int OFF_H3  = 8340;         // 16
constexpr int OFF_H4  = 8356;         // 8
constexpr int OFF_U   = 8364;         // 18432-float union region
constexpr int SMEM_FLOATS = OFF_U + 18432;   // 26796 floats = 107184 bytes

// union phase-A sub-offsets
constexpr int UA_TH = OFF_U + 8192;   // theta [81][32]
constexpr int UA_PH = OFF_U + 10784;  // phi   [32][81]
constexpr int UA_G  = OFF_U + 13376;  // g     [81][32]
constexpr int UA_PS = OFF_U + 15968;  // softmax scratch 8 warps x 96
constexpr int UA_WO = OFF_U + 6144;   // woT
constexpr int UA_YT = OFF_U;          // yT [32][84] (overwrites dead wtT/wpT)
// union phase-C sub-offsets
constexpr int UC_W3  = OFF_U;         // 2304
constexpr int UC_FW2 = OFF_U + 2304;  // 2048
constexpr int UC_FW3 = OFF_U + 4352;  // 512
constexpr int UC_FW4 = OFF_U + 4864;  // 128
constexpr int UC_FWO = OFF_U + 4992;  // 16
constexpr int UC_FW1 = OFF_U + 5008;  // 12800

__global__ __launch_bounds__(256, 2)
void braggnn_kernel(const float* __restrict__ x,
                    const float* __restrict__ w1,  const float* __restrict__ b1,
                    const float* __restrict__ bt,  const float* __restrict__ bp,
                    const float* __restrict__ bg,  const float* __restrict__ bo,
                    const float* __restrict__ b2,  const float* __restrict__ b3,
                    const float* __restrict__ fw1, const float* __restrict__ fb1,
                    const float* __restrict__ fw2, const float* __restrict__ fb2,
                    const float* __restrict__ fw3, const float* __restrict__ fb3,
                    const float* __restrict__ fw4, const float* __restrict__ fb4,
                    const float* __restrict__ fwo, const float* __restrict__ fbo,
                    float* __restrict__ out)
{
    extern __shared__ float sm[];
    const int tid  = threadIdx.x;
    const int warp = tid >> 5, lane = tid & 31;
    const int b    = blockIdx.x;

    // ---------------- stage input + phase-A weights ----------------
    for (int i = tid; i < 121; i += 256) sm[OFF_XIN + i] = x[b * 121 + i];
    for (int i = tid; i < 576; i += 256) sm[OFF_W1 + i]  = w1[i];
    if (tid < 64) { sm[OFF_B1 + tid] = b1[tid]; sm[OFF_BO + tid] = bo[tid]; sm[OFF_FB1 + tid] = fb1[tid]; }
    if (tid < 32) { sm[OFF_BT + tid] = bt[tid]; sm[OFF_BP + tid] = bp[tid]; sm[OFF_BG + tid] = bg[tid];
                    sm[OFF_B2 + tid] = b2[tid]; sm[OFF_FB2 + tid] = fb2[tid]; }
    if (tid < 16)  sm[OFF_FB3 + tid] = fb3[tid];
    if (tid < 8)  { sm[OFF_B3 + tid] = b3[tid]; sm[OFF_FB4 + tid] = fb4[tid]; }
    if (tid < 2)   sm[OFF_FBO + tid] = fbo[tid];
    for (int i = tid; i < 6144; i += 256) sm[OFF_U + i]        = g_qkvT[i];
    for (int i = tid; i < 2048; i += 256) sm[UA_WO + i]        = g_woT[i];
    __syncthreads();

    // ---------------- conv1: [1,11,11] -> [64,9,9] ----------------
    {
        int p  = tid & 127;                       // 0..127; only p<81 active
        if (p < 81) {
            int yy = p / 9, xx = p - yy * 9;      // one div per thread
            const float* xr = &sm[OFF_XIN + yy * 11 + xx];
            float x0 = xr[0],  x1 = xr[1],  x2 = xr[2];
            float x3 = xr[11], x4 = xr[12], x5 = xr[13];
            float x6 = xr[22], x7 = xr[23], x8 = xr[24];
            int c0 = (tid >> 7) ? 32 : 0;         // two thread-halves split channels
            #pragma unroll 8
            for (int c = c0; c < c0 + 32; c++) {
                const float* wr = &sm[OFF_W1 + c * 9];
                float acc = sm[OFF_B1 + c];
                acc += wr[0] * x0 + wr[1] * x1 + wr[2] * x2;
                acc += wr[3] * x3 + wr[4] * x4 + wr[5] * x5;
                acc += wr[6] * x6 + wr[7] * x7 + wr[8] * x8;
                sm[OFF_A1 + c * 84 + p] = acc;
            }
        }
    }
    __syncthreads();

    // ---------------- theta / phi / g projections (packed f32x2) ----------
    for (int task = warp; task < 63; task += 8) {
        int mat = task / 21, sg = task - mat * 21, s0 = sg * 4;
        const float* W = &sm[OFF_U + mat * 2048];
        float bias = (mat == 0) ? sm[OFF_BT + lane] : (mat == 1) ? sm[OFF_BP + lane] : sm[OFF_BG + lane];
        unsigned long long acc01 = pk2(bias, bias), acc23 = pk2(bias, bias);
        #pragma unroll 8
        for (int c = 0; c < 64; c++) {
            float  wv = W[c * 32 + lane];
            unsigned long long wvv = pk2(wv, wv);
            float4 av = *(const float4*)&sm[OFF_A1 + c * 84 + s0];
            acc01 = fma2(wvv, pk2(av.x, av.y), acc01);
            acc23 = fma2(wvv, pk2(av.z, av.w), acc23);
        }
        float a0, a1v, a2v, a3v;
        upk2(acc01, a0, a1v); upk2(acc23, a2v, a3v);
        int nv = 81 - s0; if (nv > 4) nv = 4;
        if (mat == 1) {                         // phi stored [o][81]
            float* P = &sm[UA_PH + lane * 81 + s0];
            P[0] = a0; if (nv > 1) P[1] = a1v; if (nv > 2) P[2] = a2v; if (nv > 3) P[3] = a3v;
        } else {                                // theta / g stored [s][32]
            float* T = &sm[(mat == 0 ? UA_TH : UA_G) + s0 * 32 + lane];
            T[0] = a0; if (nv > 1) T[32] = a1v; if (nv > 2) T[64] = a2v; if (nv > 3) T[96] = a3v;
        }
    }
    __syncthreads();

    // ---------------- attention rows + y  (packed f32x2) ----------------
    {
        const float* PH = &sm[UA_PH];
        const float* G  = &sm[UA_G];
        float*       PS = &sm[UA_PS + warp * 96];
        const bool v2 = (lane < 17);
        for (int s = warp; s < 81; s += 8) {
            const float* TH = &sm[UA_TH + s * 32];
            // scores: (sc0,sc1) packed, sc2 scalar — each packed lane is the
            // identical scalar chain (bitwise-equal to the scalar version).
            unsigned long long s01 = pk2(0.f, 0.f);
            float sc2 = 0.f;
            #pragma unroll 8
            for (int i = 0; i < 32; i++) {
                float th = TH[i];
                const float* pr = &PH[i * 81 + lane];
                s01 = fma2(pk2(th, th), pk2(pr[0], pr[32]), s01);
                sc2 += th * pr[64];      // junk for lane>=17, in-bounds smem, masked below
            }
            float sc0, sc1; upk2(s01, sc0, sc1);
            if (!v2) sc2 = -1e30f;
            float m = fmaxf(sc0, fmaxf(sc1, sc2));
            #pragma unroll
            for (int off = 16; off; off >>= 1) m = fmaxf(m, __shfl_xor_sync(0xffffffffu, m, off));
            float e0 = __expf(sc0 - m), e1 = __expf(sc1 - m), e2 = v2 ? __expf(sc2 - m) : 0.f;
            float ssum = e0 + e1 + e2;
            #pragma unroll
            for (int off = 16; off; off >>= 1) ssum += __shfl_xor_sync(0xffffffffu, ssum, off);
            float inv = 1.0f / ssum;
            PS[lane] = e0 * inv; PS[lane + 32] = e1 * inv; if (v2) PS[lane + 64] = e2 * inv;
            __syncwarp();
            // y[s][lane] = sum_t p[t] * g[t][lane]; packed accumulator:
            // lo sums terms t0,t0+2.. (even-in-group), hi sums odd-in-group.
            unsigned long long accP = pk2(0.f, 0.f);
            #pragma unroll 5
            for (int t0 = 0; t0 < 80; t0 += 4) {
                float4 p4 = *(const float4*)&PS[t0];
                const float* gp = &G[t0 * 32 + lane];
                accP = fma2(pk2(p4.x, p4.y), pk2(gp[0],  gp[32]), accP);
                accP = fma2(pk2(p4.z, p4.w), pk2(gp[64], gp[96]), accP);
            }
            float acc = sum2(accP) + PS[80] * G[80 * 32 + lane];
            sm[UA_YT + lane * 84 + s] = acc;    // yT[i][s]  (wtT/wpT are dead)
            __syncwarp();                       // protect PS before next row rewrites it
        }
    }
    __syncthreads();

    // ---------------- wo projection + residual + lrelu (packed f32x2) -----
    for (int idx = tid; idx < 1344; idx += 256) {      // 64 c * 21 s-groups
        int c = idx & 63, sg = idx >> 6, s0 = sg * 4;
        const float* WO = &sm[UA_WO];
        const float* YT = &sm[UA_YT];
        float bv = sm[OFF_BO + c];
        unsigned long long acc01 = pk2(bv, bv), acc23 = pk2(bv, bv);
        #pragma unroll 8
        for (int i = 0; i < 32; i++) {
            float  wv = WO[i * 64 + c];
            unsigned long long wvv = pk2(wv, wv);
            float4 y4 = *(const float4*)&YT[i * 84 + s0];
            acc01 = fma2(wvv, pk2(y4.x, y4.y), acc01);
            acc23 = fma2(wvv, pk2(y4.z, y4.w), acc23);
        }
        float a0, a1v, a2v, a3v;
        upk2(acc01, a0, a1v); upk2(acc23, a2v, a3v);
        int nv = 81 - s0; if (nv > 4) nv = 4;
        float* A = &sm[OFF_A1 + c * 84 + s0];
        { float v = A[0] + a0;  A[0] = lrelu(v); }
        if (nv > 1) { float v = A[1] + a1v; A[1] = lrelu(v); }
        if (nv > 2) { float v = A[2] + a2v; A[2] = lrelu(v); }
        if (nv > 3) { float v = A[3] + a3v; A[3] = lrelu(v); }
    }
    __syncthreads();

    // ---------------- stage w2 (overwrites attention union) ----------------
    for (int i = tid; i < 18432; i += 256) sm[OFF_U + i] = g_w2T[i];
    __syncthreads();

    // ---------------- conv2: [64,9,9] -> [32,7,7]  (packed f32x2) ----------
    // lo half of every accumulator sums even-ci contributions, hi sums odd-ci.
    if (warp < 7) {
        const int co = lane, yy = warp;
        float bv = sm[OFF_B2 + co];
        unsigned long long acc0 = pk2(bv, 0.f), acc1 = pk2(bv, 0.f),
                           acc2 = pk2(bv, 0.f), acc3 = pk2(bv, 0.f),
                           acc4 = pk2(bv, 0.f), acc5 = pk2(bv, 0.f),
                           acc6 = pk2(bv, 0.f);
        #pragma unroll 2
        for (int ci = 0; ci < 64; ci += 2) {
            const float* WpL = &sm[OFF_U + ci * 288 + co];        // even ci
            const float* WpR = WpL + 288;                         // odd  ci
            const float* RLb = &sm[OFF_A1 + ci * 84];
            const float* RRb = RLb + 84;
            #pragma unroll
            for (int ky = 0; ky < 3; ky++) {
                unsigned long long wA = pk2(WpL[(ky * 3 + 0) * 32], WpR[(ky * 3 + 0) * 32]);
                unsigned long long wB = pk2(WpL[(ky * 3 + 1) * 32], WpR[(ky * 3 + 1) * 32]);
                unsigned long long wC = pk2(WpL[(ky * 3 + 2) * 32], WpR[(ky * 3 + 2) * 32]);
                const float* rl = RLb + (yy + ky) * 9;
                const float* rr = RRb + (yy + ky) * 9;
                unsigned long long t0 = pk2(rl[0], rr[0]);
                unsigned long long t1 = pk2(rl[1], rr[1]);
                unsigned long long t2 = pk2(rl[2], rr[2]);
                unsigned long long t3 = pk2(rl[3], rr[3]);
                unsigned long long t4 = pk2(rl[4], rr[4]);
                unsigned long long t5 = pk2(rl[5], rr[5]);
                unsigned long long t6 = pk2(rl[6], rr[6]);
                unsigned long long t7 = pk2(rl[7], rr[7]);
                unsigned long long t8 = pk2(rl[8], rr[8]);
                acc0 = fma2(wA, t0, acc0); acc0 = fma2(wB, t1, acc0); acc0 = fma2(wC, t2, acc0);
                acc1 = fma2(wA, t1, acc1); acc1 = fma2(wB, t2, acc1); acc1 = fma2(wC, t3, acc1);
                acc2 = fma2(wA, t2, acc2); acc2 = fma2(wB, t3, acc2); acc2 = fma2(wC, t4, acc2);
                acc3 = fma2(wA, t3, acc3); acc3 = fma2(wB, t4, acc3); acc3 = fma2(wC, t5, acc3);
                acc4 = fma2(wA, t4, acc4); acc4 = fma2(wB, t5, acc4); acc4 = fma2(wC, t6, acc4);
                acc5 = fma2(wA, t5, acc5); acc5 = fma2(wB, t6, acc5); acc5 = fma2(wC, t7, acc5);
                acc6 = fma2(wA, t6, acc6); acc6 = fma2(wB, t7, acc6); acc6 = fma2(wC, t8, acc6);
            }
        }
        float* O = &sm[OFF_A2 + co * 49 + yy * 7];
        O[0] = lrelu(sum2(acc0)); O[1] = lrelu(sum2(acc1)); O[2] = lrelu(sum2(acc2));
        O[3] = lrelu(sum2(acc3)); O[4] = lrelu(sum2(acc4)); O[5] = lrelu(sum2(acc5));
        O[6] = lrelu(sum2(acc6));
    }
    __syncthreads();

    // ---------------- stage phase-C weights (overwrites w2) ----------------
    for (int i = tid; i < 2304;  i += 256) sm[UC_W3 + i]  = g_w3T[i];
    for (int i = tid; i < 2048;  i += 256) sm[UC_FW2 + i] = fw2[i];
    for (int i = tid; i < 512;   i += 256) sm[UC_FW3 + i] = fw3[i];
    if (tid < 128) sm[UC_FW4 + tid] = fw4[tid];
    if (tid < 16)  sm[UC_FWO + tid] = fwo[tid];
    for (int i = tid; i < 12800; i += 256) sm[UC_FW1 + i] = fw1[i];
    __syncthreads();

    // ---------------- conv3: [32,7,7] -> [8,5,5] -> flat 200 (packed) ------
    // lo half sums even-ci contributions, hi sums odd-ci.
    if (tid < 200) {
        int co = tid / 25, p = tid - co * 25, yy = p / 5, xx = p - yy * 5;
        unsigned long long acc = pk2(sm[OFF_B3 + co], 0.f);
        #pragma unroll 4
        for (int ci = 0; ci < 32; ci += 2) {
            const float* WL = &sm[UC_W3 + ci * 72 + co];
            const float* WR = WL + 72;
            const float* RL = &sm[OFF_A2 + ci * 49 + yy * 7 + xx];
            const float* RR = RL + 49;
            acc = fma2(pk2(WL[0],  WR[0]),  pk2(RL[0],  RR[0]),  acc);
            acc = fma2(pk2(WL[8],  WR[8]),  pk2(RL[1],  RR[1]),  acc);
            acc = fma2(pk2(WL[16], WR[16]), pk2(RL[2],  RR[2]),  acc);
            acc = fma2(pk2(WL[24], WR[24]), pk2(RL[7],  RR[7]),  acc);
            acc = fma2(pk2(WL[32], WR[32]), pk2(RL[8],  RR[8]),  acc);
            acc = fma2(pk2(WL[40], WR[40]), pk2(RL[9],  RR[9]),  acc);
            acc = fma2(pk2(WL[48], WR[48]), pk2(RL[14], RR[14]), acc);
            acc = fma2(pk2(WL[56], WR[56]), pk2(RL[15], RR[15]), acc);
            acc = fma2(pk2(WL[64], WR[64]), pk2(RL[16], RR[16]), acc);
        }
        sm[OFF_A3 + tid] = lrelu(sum2(acc));
    }
    __syncthreads();

    // ---------------- FC stack ----------------
    if (tid < 64) {
        const float* W = &sm[UC_FW1 + tid * 200];
        float acc = sm[OFF_FB1 + tid];
        #pragma unroll 10
        for (int j = 0; j < 200; j += 4) {
            float4 w4 = *(const float4*)&W[j];
            float4 a4 = *(const float4*)&sm[OFF_A3 + j];
            acc += w4.x * a4.x + w4.y * a4.y + w4.z * a4.z + w4.w * a4.w;
        }
        sm[OFF_H1 + tid] = lrelu(acc);
    }
    __syncthreads();
    if (tid < 32) {
        const float* W = &sm[UC_FW2 + tid * 64];
        float acc = sm[OFF_FB2 + tid];
        #pragma unroll
        for (int j = 0; j < 64; j += 4) {
            float4 w4 = *(const float4*)&W[j];
            float4 h4 = *(const float4*)&sm[OFF_H1 + j];
            acc += w4.x * h4.x + w4.y * h4.y + w4.z * h4.z + w4.w * h4.w;
        }
        sm[OFF_H2 + tid] = lrelu(acc);
    }
    __syncthreads();
    if (tid < 16) {
        const float* W = &sm[UC_FW3 + tid * 32];
        float acc = sm[OFF_FB3 + tid];
        #pragma unroll
        for (int j = 0; j < 32; j += 4) {
            float4 w4 = *(const float4*)&W[j];
            float4 h4 = *(const float4*)&sm[OFF_H2 + j];
            acc += w4.x * h4.x + w4.y * h4.y + w4.z * h4.z + w4.w * h4.w;
        }
        sm[OFF_H3 + tid] = lrelu(acc);
    }
    __syncthreads();
    if (tid < 8) {
        const float* W = &sm[UC_FW4 + tid * 16];
        float acc = sm[OFF_FB4 + tid];
        #pragma unroll
        for (int j = 0; j < 16; j++) acc += W[j] * sm[OFF_H3 + j];
        sm[OFF_H4 + tid] = lrelu(acc);
    }
    __syncthreads();
    if (tid < 2) {
        const float* W = &sm[UC_FWO + tid * 8];
        float acc = sm[OFF_FBO + tid];
        #pragma unroll
        for (int j = 0; j < 8; j++) acc += W[j] * sm[OFF_H4 + j];
        out[b * 2 + tid] = acc;
    }
}

extern "C" void kernel_launch(void* const* d_in, const int* in_sizes, int n_in,
                              void* d_out, int out_size)
{
    const float* x   = (const float*)d_in[0];
    const float* w1  = (const float*)d_in[1];
    const float* b1  = (const float*)d_in[2];
    const float* wt  = (const float*)d_in[3];
    const float* bt  = (const float*)d_in[4];
    const float* wp  = (const float*)d_in[5];
    const float* bp  = (const float*)d_in[6];
    const float* wg  = (const float*)d_in[7];
    const float* bg  = (const float*)d_in[8];
    const float* wo  = (const float*)d_in[9];
    const float* bo  = (const float*)d_in[10];
    const float* w2  = (const float*)d_in[11];
    const float* b2  = (const float*)d_in[12];
    const float* w3  = (const float*)d_in[13];
    const float* b3  = (const float*)d_in[14];
    const float* fw1 = (const float*)d_in[15];
    const float* fb1 = (const float*)d_in[16];
    const float* fw2 = (const float*)d_in[17];
    const float* fb2 = (const float*)d_in[18];
    const float* fw3 = (const float*)d_in[19];
    const float* fb3 = (const float*)d_in[20];
    const float* fw4 = (const float*)d_in[21];
    const float* fb4 = (const float*)d_in[22];
    const float* fwo = (const float*)d_in[23];
    const float* fbo = (const float*)d_in[24];
    float* out = (float*)d_out;

    const int B = out_size / 2;

    cudaFuncSetAttribute(braggnn_kernel,
                         cudaFuncAttributeMaxDynamicSharedMemorySize,
                         SMEM_FLOATS * (int)sizeof(float));

    prep_kernel<<<24, 256>>>(wt, wp, wg, wo, w2, w3);
    braggnn_kernel<<<B, 256, SMEM_FLOATS * sizeof(float)>>>(
        x, w1, b1, bt, bp, bg, bo, b2, b3,
        fw1, fb1, fw2, fb2, fw3, fb3, fw4, fb4, fwo, fbo, out);
}

// round 9
// speedup vs baseline: 1.2878x; 1.2878x over previous
#include <cuda_runtime.h>

// ---------------------------------------------------------------------------
// BraggNN fused forward.  One sample per block, 256 threads.
// R5 insight: kernel is L1/shared-wavefront bound (L1=90%, fma=25%).
// This round: wide/interleaved layouts to minimize LDS wavefronts.
// ---------------------------------------------------------------------------

#define SLOPE 0.01f
typedef unsigned long long ull;

// pre-transformed weights (device globals: allocation-free)
__device__ float g_w1p [768];    // [c(64)][12]  rows of 9 padded to 12
__device__ float g_qkvT[6144];   // wtT/wpT/wgT : [c(64)][o(32)] each
__device__ float g_woT [2048];   // woT : [i(32)][c(64)]
__device__ float g_w2p [20480];  // [pair(32)][co(32)][20]: j=2k+(ci&1) -> w2[co][2p+(j&1)][k]
__device__ float g_w3T [2304];   // w3T : [ci(32)][k(9)][co(8)]

__device__ __forceinline__ float lrelu(float v) { return v > 0.f ? v : SLOPE * v; }

__device__ __forceinline__ ull pk2(float lo, float hi) {
    ull r; asm("mov.b64 %0, {%1, %2};" : "=l"(r) : "f"(lo), "f"(hi)); return r;
}
__device__ __forceinline__ ull fma2(ull a, ull b, ull c) {
    ull d; asm("fma.rn.f32x2 %0, %1, %2, %3;" : "=l"(d) : "l"(a), "l"(b), "l"(c)); return d;
}
__device__ __forceinline__ void upk2(ull v, float& lo, float& hi) {
    asm("mov.b64 {%0, %1}, %2;" : "=f"(lo), "=f"(hi) : "l"(v));
}
__device__ __forceinline__ float sum2(ull v) { float lo, hi; upk2(v, lo, hi); return lo + hi; }

__global__ void prep_kernel(const float* __restrict__ w1,
                            const float* __restrict__ wt, const float* __restrict__ wp,
                            const float* __restrict__ wg, const float* __restrict__ wo,
                            const float* __restrict__ w2, const float* __restrict__ w3)
{
    int t = blockIdx.x * blockDim.x + threadIdx.x;
    int n = gridDim.x * blockDim.x;
    for (int i = t; i < 768; i += n) { int c = i / 12, j = i - c * 12;
        g_w1p[i] = (j < 9) ? w1[c * 9 + j] : 0.f; }
    for (int i = t; i < 2048; i += n) { int o = i & 31, c = i >> 5;
        g_qkvT[i]        = wt[o * 64 + c];
        g_qkvT[2048 + i] = wp[o * 64 + c];
        g_qkvT[4096 + i] = wg[o * 64 + c]; }
    for (int i = t; i < 2048; i += n) { int c = i & 63, o = i >> 6;
        g_woT[i] = wo[c * 32 + o]; }
    for (int i = t; i < 20480; i += n) {
        int pair = i / 640, rem = i - pair * 640, co = rem / 20, j = rem - co * 20;
        g_w2p[i] = (j < 18) ? w2[(co * 64 + 2 * pair + (j & 1)) * 9 + (j >> 1)] : 0.f; }
    for (int i = t; i < 2304; i += n) { int o = i & 7, k = (i >> 3) % 9, ci = i / 72;
        g_w3T[i] = w3[(o * 32 + ci) * 9 + k]; }
}

// ---- shared memory layout (float offsets) ----
constexpr int OFF_XIN = 0;            // 121 (pad 128)
constexpr int OFF_W1P = 128;          // 768
constexpr int OFF_B1  = 896;          // 64
constexpr int OFF_BT  = 960;          // 32
constexpr int OFF_BP  = 992;          // 32
constexpr int OFF_BG  = 1024;         // 32
constexpr int OFF_BO  = 1056;         // 64
constexpr int OFF_B2  = 1120;         // 32
constexpr int OFF_B3  = 1152;         // 8 (pad 16)
constexpr int OFF_FB1 = 1168;         // 64
constexpr int OFF_FB2 = 1232;         // 32
constexpr int OFF_FB3 = 1264;         // 16
constexpr int OFF_FB4 = 1280;         // 8
constexpr int OFF_FBO = 1288;         // 2 (pad 4)
constexpr int OFF_A1  = 1292;         // [64][84] conv1 out (residual source)
constexpr int OFF_A2  = 6668;         // [32][49]
constexpr int OFF_A3  = 8236;         // 200 (pad 208)
constexpr int OFF_H1  = 8444;         // 64
constexpr int OFF_H2  = 8508;         // 32
constexpr int OFF_H3  = 8540;         // 16
constexpr int OFF_H4  = 8556;         // 8
constexpr int OFF_U   = 8564;         // 18432-float union region
constexpr int SMEM_FLOATS = OFF_U + 18432;   // 26996 floats = 107984 bytes

// phase A (NLB)
constexpr int UA_QKV = OFF_U;          // 6144 (wtT/wpT/wgT)
constexpr int UA_WO  = OFF_U + 6144;   // 2048
constexpr int UA_TH  = OFF_U + 8192;   // theta [81][32]
constexpr int UA_PH  = OFF_U + 10784;  // phi   [32][81]
constexpr int UA_G   = OFF_U + 13376;  // g     [81][32]
constexpr int UA_PS  = OFF_U + 15968;  // 8 warps x 192 (two softmax rows)
constexpr int UA_YT  = OFF_U;          // yT [32][84] (over dead wtT/wpT-head)
// phase B (conv2)
constexpr int UB_A1P = OFF_U + 8192;   // [pair(32)][row(9)][24] = 6912 (over dead TH/PH/G)
constexpr int UB_W2  = OFF_U;          // chunk <=12 pairs x 640 = 7680 (over dead YT/WO)
// phase C
constexpr int UC_W3  = OFF_U;          // 2304
constexpr int UC_FW2 = OFF_U + 2304;   // 2048
constexpr int UC_FW3 = OFF_U + 4352;   // 512
constexpr int UC_FW4 = OFF_U + 4864;   // 128
constexpr int UC_FWO = OFF_U + 4992;   // 16

__global__ __launch_bounds__(256, 2)
void braggnn_kernel(const float* __restrict__ x,
                    const float* __restrict__ b1,
                    const float* __restrict__ bt,  const float* __restrict__ bp,
                    const float* __restrict__ bg,  const float* __restrict__ bo,
                    const float* __restrict__ b2,  const float* __restrict__ b3,
                    const float* __restrict__ fw1, const float* __restrict__ fb1,
                    const float* __restrict__ fw2, const float* __restrict__ fb2,
                    const float* __restrict__ fw3, const float* __restrict__ fb3,
                    const float* __restrict__ fw4, const float* __restrict__ fb4,
                    const float* __restrict__ fwo, const float* __restrict__ fbo,
                    float* __restrict__ out)
{
    extern __shared__ float sm[];
    const int tid  = threadIdx.x;
    const int warp = tid >> 5, lane = tid & 31;
    const int b    = blockIdx.x;

    // ---------------- stage input + phase-A weights (wide) ----------------
    for (int i = tid; i < 121; i += 256) sm[OFF_XIN + i] = x[b * 121 + i];
    if (tid < 192) ((float4*)&sm[OFF_W1P])[tid] = ((const float4*)g_w1p)[tid];
    if (tid < 64) { sm[OFF_B1 + tid] = b1[tid]; sm[OFF_BO + tid] = bo[tid]; sm[OFF_FB1 + tid] = fb1[tid]; }
    if (tid < 32) { sm[OFF_BT + tid] = bt[tid]; sm[OFF_BP + tid] = bp[tid]; sm[OFF_BG + tid] = bg[tid];
                    sm[OFF_B2 + tid] = b2[tid]; sm[OFF_FB2 + tid] = fb2[tid]; }
    if (tid < 16)  sm[OFF_FB3 + tid] = fb3[tid];
    if (tid < 8)  { sm[OFF_B3 + tid] = b3[tid]; sm[OFF_FB4 + tid] = fb4[tid]; }
    if (tid < 2)   sm[OFF_FBO + tid] = fbo[tid];
    for (int i = tid; i < 1536; i += 256) ((float4*)&sm[UA_QKV])[i] = ((const float4*)g_qkvT)[i];
    for (int i = tid; i < 512;  i += 256) ((float4*)&sm[UA_WO])[i]  = ((const float4*)g_woT)[i];
    __syncthreads();

    // ---------------- conv1: [1,11,11] -> [64,9,9] ----------------
    {
        int p = tid & 127;
        if (p < 81) {
            int yy = p / 9, xx = p - yy * 9;
            const float* xr = &sm[OFF_XIN + yy * 11 + xx];
            float x0 = xr[0],  x1 = xr[1],  x2 = xr[2];
            float x3 = xr[11], x4 = xr[12], x5 = xr[13];
            float x6 = xr[22], x7 = xr[23], x8 = xr[24];
            int c0 = (tid >> 7) ? 32 : 0;
            #pragma unroll 8
            for (int c = c0; c < c0 + 32; c++) {
                const float* wr = &sm[OFF_W1P + c * 12];
                float4 wa = *(const float4*)wr;
                float4 wb = *(const float4*)(wr + 4);
                float  w8 = wr[8];
                float acc = sm[OFF_B1 + c];
                acc += wa.x * x0 + wa.y * x1 + wa.z * x2 + wa.w * x3;
                acc += wb.x * x4 + wb.y * x5 + wb.z * x6 + wb.w * x7 + w8 * x8;
                sm[OFF_A1 + c * 84 + p] = acc;
            }
        }
    }
    __syncthreads();

    // ------- theta/phi/g fused projections (shared act broadcast) -------
    for (int sg = warp; sg < 21; sg += 8) {
        int s0 = sg * 4;
        const float* Wt = &sm[UA_QKV];
        const float* Wp = &sm[UA_QKV + 2048];
        const float* Wg = &sm[UA_QKV + 4096];
        float btv = sm[OFF_BT + lane], bpv = sm[OFF_BP + lane], bgv = sm[OFF_BG + lane];
        ull t01 = pk2(btv, btv), t23 = pk2(btv, btv);
        ull p01 = pk2(bpv, bpv), p23 = pk2(bpv, bpv);
        ull g01 = pk2(bgv, bgv), g23 = pk2(bgv, bgv);
        #pragma unroll 4
        for (int c = 0; c < 64; c++) {
            float4 av = *(const float4*)&sm[OFF_A1 + c * 84 + s0];
            ull a01 = pk2(av.x, av.y), a23 = pk2(av.z, av.w);
            float wv = Wt[c * 32 + lane]; ull w = pk2(wv, wv);
            t01 = fma2(w, a01, t01); t23 = fma2(w, a23, t23);
            wv = Wp[c * 32 + lane]; w = pk2(wv, wv);
            p01 = fma2(w, a01, p01); p23 = fma2(w, a23, p23);
            wv = Wg[c * 32 + lane]; w = pk2(wv, wv);
            g01 = fma2(w, a01, g01); g23 = fma2(w, a23, g23);
        }
        int nv = 81 - s0; if (nv > 4) nv = 4;
        float v0, v1, v2x, v3;
        upk2(t01, v0, v1); upk2(t23, v2x, v3);
        { float* T = &sm[UA_TH + s0 * 32 + lane];
          T[0] = v0; if (nv > 1) T[32] = v1; if (nv > 2) T[64] = v2x; if (nv > 3) T[96] = v3; }
        upk2(p01, v0, v1); upk2(p23, v2x, v3);
        { float* P = &sm[UA_PH + lane * 81 + s0];
          P[0] = v0; if (nv > 1) P[1] = v1; if (nv > 2) P[2] = v2x; if (nv > 3) P[3] = v3; }
        upk2(g01, v0, v1); upk2(g23, v2x, v3);
        { float* G = &sm[UA_G + s0 * 32 + lane];
          G[0] = v0; if (nv > 1) G[32] = v1; if (nv > 2) G[64] = v2x; if (nv > 3) G[96] = v3; }
    }
    __syncthreads();

    // ------- attention: 2 rows per iteration share PH / G loads -------
    {
        const float* PH = &sm[UA_PH];
        const float* G  = &sm[UA_G];
        float* PSA = &sm[UA_PS + warp * 192];
        float* PSB = PSA + 96;
        const bool v2 = (lane < 17);
        for (int sA = warp; sA < 81; sA += 16) {
            int sB = sA + 8; bool hasB = (sB < 81);
            const float* THa = &sm[UA_TH + sA * 32];
            const float* THb = &sm[UA_TH + (hasB ? sB : sA) * 32];
            ull a01 = pk2(0.f, 0.f), b01 = pk2(0.f, 0.f);
            float a2s = 0.f, b2s = 0.f;
            #pragma unroll 8
            for (int i = 0; i < 32; i++) {
                const float* pr = &PH[i * 81 + lane];
                ull pv = pk2(pr[0], pr[32]); float p2 = pr[64];
                float ta = THa[i], tb = THb[i];
                a01 = fma2(pk2(ta, ta), pv, a01); a2s += ta * p2;
                b01 = fma2(pk2(tb, tb), pv, b01); b2s += tb * p2;
            }
            float a0, a1; upk2(a01, a0, a1);
            float b0, b1; upk2(b01, b0, b1);
            if (!v2) { a2s = -1e30f; b2s = -1e30f; }
            float mA = fmaxf(a0, fmaxf(a1, a2s));
            float mB = fmaxf(b0, fmaxf(b1, b2s));
            #pragma unroll
            for (int off = 16; off; off >>= 1) {
                mA = fmaxf(mA, __shfl_xor_sync(0xffffffffu, mA, off));
                mB = fmaxf(mB, __shfl_xor_sync(0xffffffffu, mB, off));
            }
            float eA0 = __expf(a0 - mA), eA1 = __expf(a1 - mA), eA2 = v2 ? __expf(a2s - mA) : 0.f;
            float eB0 = __expf(b0 - mB), eB1 = __expf(b1 - mB), eB2 = v2 ? __expf(b2s - mB) : 0.f;
            float sAu = eA0 + eA1 + eA2, sBu = eB0 + eB1 + eB2;
            #pragma unroll
            for (int off = 16; off; off >>= 1) {
                sAu += __shfl_xor_sync(0xffffffffu, sAu, off);
                sBu += __shfl_xor_sync(0xffffffffu, sBu, off);
            }
            float invA = 1.0f / sAu, invB = 1.0f / sBu;
            PSA[lane] = eA0 * invA; PSA[lane + 32] = eA1 * invA; if (v2) PSA[lane + 64] = eA2 * invA;
            PSB[lane] = eB0 * invB; PSB[lane + 32] = eB1 * invB; if (v2) PSB[lane + 64] = eB2 * invB;
            __syncwarp();
            ull accA = pk2(0.f, 0.f), accB = pk2(0.f, 0.f);
            #pragma unroll 5
            for (int t0 = 0; t0 < 80; t0 += 4) {
                const float* gp = &G[t0 * 32 + lane];
                ull gq01 = pk2(gp[0],  gp[32]);
                ull gq23 = pk2(gp[64], gp[96]);
                float4 pa = *(const float4*)&PSA[t0];
                float4 pb = *(const float4*)&PSB[t0];
                accA = fma2(pk2(pa.x, pa.y), gq01, accA);
                accA = fma2(pk2(pa.z, pa.w), gq23, accA);
                accB = fma2(pk2(pb.x, pb.y), gq01, accB);
                accB = fma2(pk2(pb.z, pb.w), gq23, accB);
            }
            float gT = G[80 * 32 + lane];
            sm[UA_YT + lane * 84 + sA] = sum2(accA) + PSA[80] * gT;
            if (hasB) sm[UA_YT + lane * 84 + sB] = sum2(accB) + PSB[80] * gT;
            __syncwarp();
        }
    }
    __syncthreads();

    // ---- wo projection + residual + lrelu, written to interleaved A1P ----
    for (int idx = tid; idx < 1344; idx += 256) {      // 64 c * 21 s-groups
        int c = idx & 63, sg = idx >> 6, s0 = sg * 4;
        const float* WO = &sm[UA_WO];
        const float* YT = &sm[UA_YT];
        float bv = sm[OFF_BO + c];
        ull acc01 = pk2(bv, bv), acc23 = pk2(bv, bv);
        #pragma unroll 8
        for (int i = 0; i < 32; i++) {
            float wv = WO[i * 64 + c]; ull w = pk2(wv, wv);
            float4 y4 = *(const float4*)&YT[i * 84 + s0];
            acc01 = fma2(w, pk2(y4.x, y4.y), acc01);
            acc23 = fma2(w, pk2(y4.z, y4.w), acc23);
        }
        float a0, a1v, a2v, a3v;
        upk2(acc01, a0, a1v); upk2(acc23, a2v, a3v);
        int nv = 81 - s0; if (nv > 4) nv = 4;
        const float* A = &sm[OFF_A1 + c * 84 + s0];      // residual source
        float* AP = &sm[UB_A1P + (c >> 1) * 216 + (c & 1)];
        int r = s0 / 9, col = s0 - r * 9;
        AP[r * 24 + col * 2] = lrelu(A[0] + a0);
        col++; if (col == 9) { col = 0; r++; }
        if (nv > 1) { AP[r * 24 + col * 2] = lrelu(A[1] + a1v); col++; if (col == 9) { col = 0; r++; } }
        if (nv > 2) { AP[r * 24 + col * 2] = lrelu(A[2] + a2v); col++; if (col == 9) { col = 0; r++; } }
        if (nv > 3) { AP[r * 24 + col * 2] = lrelu(A[3] + a3v); }
    }
    __syncthreads();

    // ---- conv2: [64,9,9] -> [32,7,7], chunked weight staging, all-wide ----
    ull c2a0, c2a1, c2a2, c2a3, c2a4, c2a5, c2a6;
    if (warp < 7) {
        float bv = sm[OFF_B2 + lane];
        c2a0 = pk2(bv, 0.f); c2a1 = pk2(bv, 0.f); c2a2 = pk2(bv, 0.f);
        c2a3 = pk2(bv, 0.f); c2a4 = pk2(bv, 0.f); c2a5 = pk2(bv, 0.f); c2a6 = pk2(bv, 0.f);
    }
    {
        int pairBase = 0;
        #pragma unroll 1
        for (int gch = 0; gch < 3; gch++) {
            int np = (gch == 0) ? 12 : 10;
            const float4* src = (const float4*)&g_w2p[pairBase * 640];
            float4* dst = (float4*)&sm[UB_W2];
            for (int i = tid; i < np * 160; i += 256) dst[i] = src[i];
            __syncthreads();
            if (warp < 7) {
                const int yy = warp;
                #pragma unroll 1
                for (int lp = 0; lp < np; lp++) {
                    const float* wb = &sm[UB_W2 + lp * 640 + lane * 20];
                    float4 wq0 = *(const float4*)(wb);
                    float4 wq1 = *(const float4*)(wb + 4);
                    float4 wq2 = *(const float4*)(wb + 8);
                    float4 wq3 = *(const float4*)(wb + 12);
                    float2 wq4 = *(const float2*)(wb + 16);
                    ull wk0 = pk2(wq0.x, wq0.y), wk1 = pk2(wq0.z, wq0.w);
                    ull wk2 = pk2(wq1.x, wq1.y), wk3 = pk2(wq1.z, wq1.w);
                    ull wk4 = pk2(wq2.x, wq2.y), wk5 = pk2(wq2.z, wq2.w);
                    ull wk6 = pk2(wq3.x, wq3.y), wk7 = pk2(wq3.z, wq3.w);
                    ull wk8 = pk2(wq4.x, wq4.y);
                    const float* ab = &sm[UB_A1P + (pairBase + lp) * 216];
                    #pragma unroll
                    for (int ky = 0; ky < 3; ky++) {
                        const float* rp = ab + (yy + ky) * 24;
                        float4 q0 = *(const float4*)(rp);
                        float4 q1 = *(const float4*)(rp + 4);
                        float4 q2 = *(const float4*)(rp + 8);
                        float4 q3 = *(const float4*)(rp + 12);
                        float2 q4 = *(const float2*)(rp + 16);
                        ull t0 = pk2(q0.x, q0.y), t1 = pk2(q0.z, q0.w);
                        ull t2 = pk2(q1.x, q1.y), t3 = pk2(q1.z, q1.w);
                        ull t4 = pk2(q2.x, q2.y), t5 = pk2(q2.z, q2.w);
                        ull t6 = pk2(q3.x, q3.y), t7 = pk2(q3.z, q3.w);
                        ull t8 = pk2(q4.x, q4.y);
                        ull wA = (ky == 0) ? wk0 : ((ky == 1) ? wk3 : wk6);
                        ull wB = (ky == 0) ? wk1 : ((ky == 1) ? wk4 : wk7);
                        ull wC = (ky == 0) ? wk2 : ((ky == 1) ? wk5 : wk8);
                        c2a0 = fma2(wA, t0, c2a0); c2a0 = fma2(wB, t1, c2a0); c2a0 = fma2(wC, t2, c2a0);
                        c2a1 = fma2(wA, t1, c2a1); c2a1 = fma2(wB, t2, c2a1); c2a1 = fma2(wC, t3, c2a1);
                        c2a2 = fma2(wA, t2, c2a2); c2a2 = fma2(wB, t3, c2a2); c2a2 = fma2(wC, t4, c2a2);
                        c2a3 = fma2(wA, t3, c2a3); c2a3 = fma2(wB, t4, c2a3); c2a3 = fma2(wC, t5, c2a3);
                        c2a4 = fma2(wA, t4, c2a4); c2a4 = fma2(wB, t5, c2a4); c2a4 = fma2(wC, t6, c2a4);
                        c2a5 = fma2(wA, t5, c2a5); c2a5 = fma2(wB, t6, c2a5); c2a5 = fma2(wC, t7, c2a5);
                        c2a6 = fma2(wA, t6, c2a6); c2a6 = fma2(wB, t7, c2a6); c2a6 = fma2(wC, t8, c2a6);
                    }
                }
            }
            __syncthreads();
            pairBase += np;
        }
    }
    if (warp < 7) {
        float* O = &sm[OFF_A2 + lane * 49 + warp * 7];
        O[0] = lrelu(sum2(c2a0)); O[1] = lrelu(sum2(c2a1)); O[2] = lrelu(sum2(c2a2));
        O[3] = lrelu(sum2(c2a3)); O[4] = lrelu(sum2(c2a4)); O[5] = lrelu(sum2(c2a5));
        O[6] = lrelu(sum2(c2a6));
    }

    // ---------------- stage phase-C weights ----------------
    for (int i = tid; i < 2304; i += 256) sm[UC_W3 + i]  = g_w3T[i];
    for (int i = tid; i < 512;  i += 256) ((float4*)&sm[UC_FW2])[i] = ((const float4*)fw2)[i];
    for (int i = tid; i < 512;  i += 256) sm[UC_FW3 + i] = fw3[i];
    if (tid < 128) sm[UC_FW4 + tid] = fw4[tid];
    if (tid < 16)  sm[UC_FWO + tid] = fwo[tid];
    __syncthreads();

    // ---------------- conv3: [32,7,7] -> [8,5,5] -> flat 200 (packed) ------
    if (tid < 200) {
        int co = tid / 25, p = tid - co * 25, yy = p / 5, xx = p - yy * 5;
        ull acc = pk2(sm[OFF_B3 + co], 0.f);
        #pragma unroll 4
        for (int ci = 0; ci < 32; ci += 2) {
            const float* WL = &sm[UC_W3 + ci * 72 + co];
            const float* WR = WL + 72;
            const float* RL = &sm[OFF_A2 + ci * 49 + yy * 7 + xx];
            const float* RR = RL + 49;
            acc = fma2(pk2(WL[0],  WR[0]),  pk2(RL[0],  RR[0]),  acc);
            acc = fma2(pk2(WL[8],  WR[8]),  pk2(RL[1],  RR[1]),  acc);
            acc = fma2(pk2(WL[16], WR[16]), pk2(RL[2],  RR[2]),  acc);
            acc = fma2(pk2(WL[24], WR[24]), pk2(RL[7],  RR[7]),  acc);
            acc = fma2(pk2(WL[32], WR[32]), pk2(RL[8],  RR[8]),  acc);
            acc = fma2(pk2(WL[40], WR[40]), pk2(RL[9],  RR[9]),  acc);
            acc = fma2(pk2(WL[48], WR[48]), pk2(RL[14], RR[14]), acc);
            acc = fma2(pk2(WL[56], WR[56]), pk2(RL[15], RR[15]), acc);
            acc = fma2(pk2(WL[64], WR[64]), pk2(RL[16], RR[16]), acc);
        }
        sm[OFF_A3 + tid] = lrelu(sum2(acc));
    }
    __syncthreads();

    // ---------------- FC stack (FC1 weights direct from global) ------------
    if (tid < 64) {
        const float4* W = (const float4*)(fw1 + tid * 200);
        float acc = sm[OFF_FB1 + tid];
        #pragma unroll 10
        for (int j = 0; j < 50; j++) {
            float4 w4 = __ldg(W + j);
            float4 a4 = *(const float4*)&sm[OFF_A3 + j * 4];
            acc += w4.x * a4.x + w4.y * a4.y + w4.z * a4.z + w4.w * a4.w;
        }
        sm[OFF_H1 + tid] = lrelu(acc);
    }
    __syncthreads();
    if (tid < 32) {
        const float* W = &sm[UC_FW2 + tid * 64];
        float acc = sm[OFF_FB2 + tid];
        #pragma unroll
        for (int j = 0; j < 64; j += 4) {
            float4 w4 = *(const float4*)&W[j];
            float4 h4 = *(const float4*)&sm[OFF_H1 + j];
            acc += w4.x * h4.x + w4.y * h4.y + w4.z * h4.z + w4.w * h4.w;
        }
        sm[OFF_H2 + tid] = lrelu(acc);
    }
    __syncthreads();
    if (tid < 16) {
        const float* W = &sm[UC_FW3 + tid * 32];
        float acc = sm[OFF_FB3 + tid];
        #pragma unroll
        for (int j = 0; j < 32; j += 4) {
            float4 w4 = *(const float4*)&W[j];
            float4 h4 = *(const float4*)&sm[OFF_H2 + j];
            acc += w4.x * h4.x + w4.y * h4.y + w4.z * h4.z + w4.w * h4.w;
        }
        sm[OFF_H3 + tid] = lrelu(acc);
    }
    __syncthreads();
    if (tid < 8) {
        const float* W = &sm[UC_FW4 + tid * 16];
        float acc = sm[OFF_FB4 + tid];
        #pragma unroll
        for (int j = 0; j < 16; j++) acc += W[j] * sm[OFF_H3 + j];
        sm[OFF_H4 + tid] = lrelu(acc);
    }
    __syncthreads();
    if (tid < 2) {
        const float* W = &sm[UC_FWO + tid * 8];
        float acc = sm[OFF_FBO + tid];
        #pragma unroll
        for (int j = 0; j < 8; j++) acc += W[j] * sm[OFF_H4 + j];
        out[b * 2 + tid] = acc;
    }
}

extern "C" void kernel_launch(void* const* d_in, const int* in_sizes, int n_in,
                              void* d_out, int out_size)
{
    const float* x   = (const float*)d_in[0];
    const float* w1  = (const float*)d_in[1];
    const float* b1  = (const float*)d_in[2];
    const float* wt  = (const float*)d_in[3];
    const float* bt  = (const float*)d_in[4];
    const float* wp  = (const float*)d_in[5];
    const float* bp  = (const float*)d_in[6];
    const float* wg  = (const float*)d_in[7];
    const float* bg  = (const float*)d_in[8];
    const float* wo  = (const float*)d_in[9];
    const float* bo  = (const float*)d_in[10];
    const float* w2  = (const float*)d_in[11];
    const float* b2  = (const float*)d_in[12];
    const float* w3  = (const float*)d_in[13];
    const float* b3  = (const float*)d_in[14];
    const float* fw1 = (const float*)d_in[15];
    const float* fb1 = (const float*)d_in[16];
    const float* fw2 = (const float*)d_in[17];
    const float* fb2 = (const float*)d_in[18];
    const float* fw3 = (const float*)d_in[19];
    const float* fb3 = (const float*)d_in[20];
    const float* fw4 = (const float*)d_in[21];
    const float* fb4 = (const float*)d_in[22];
    const float* fwo = (const float*)d_in[23];
    const float* fbo = (const float*)d_in[24];
    float* out = (float*)d_out;

    const int B = out_size / 2;

    cudaFuncSetAttribute(braggnn_kernel,
                         cudaFuncAttributeMaxDynamicSharedMemorySize,
                         SMEM_FLOATS * (int)sizeof(float));

    prep_kernel<<<24, 256>>>(w1, wt, wp, wg, wo, w2, w3);
    braggnn_kernel<<<B, 256, SMEM_FLOATS * sizeof(float)>>>(
        x, b1, bt, bp, bg, bo, b2, b3,
        fw1, fb1, fw2, fb2, fw3, fb3, fw4, fb4, fwo, fbo, out);
}

// round 14
// speedup vs baseline: 1.3602x; 1.0562x over previous
#include <cuda_runtime.h>

// ---------------------------------------------------------------------------
// BraggNN fused forward.  One sample per block, 256 threads.
// L1/shared-wavefront bound (R9: L1=86.6%, fma=32.5%).
// R10: 4-row attention tiling + 2-sg projection tiling to amortize
// shared-memory row loads over more outputs.
// ---------------------------------------------------------------------------

#define SLOPE 0.01f
typedef unsigned long long ull;

// pre-transformed weights (device globals: allocation-free)
__device__ float g_w1p [768];    // [c(64)][12]  rows of 9 padded to 12
__device__ float g_qkvT[6144];   // wtT/wpT/wgT : [c(64)][o(32)] each
__device__ float g_woT [2048];   // woT : [i(32)][c(64)]
__device__ float g_w2p [20480];  // [pair(32)][co(32)][20]: j=2k+(ci&1) -> w2[co][2p+(j&1)][k]
__device__ float g_w3T [2304];   // w3T : [ci(32)][k(9)][co(8)]

__device__ __forceinline__ float lrelu(float v) { return v > 0.f ? v : SLOPE * v; }

__device__ __forceinline__ ull pk2(float lo, float hi) {
    ull r; asm("mov.b64 %0, {%1, %2};" : "=l"(r) : "f"(lo), "f"(hi)); return r;
}
__device__ __forceinline__ ull fma2(ull a, ull b, ull c) {
    ull d; asm("fma.rn.f32x2 %0, %1, %2, %3;" : "=l"(d) : "l"(a), "l"(b), "l"(c)); return d;
}
__device__ __forceinline__ void upk2(ull v, float& lo, float& hi) {
    asm("mov.b64 {%0, %1}, %2;" : "=f"(lo), "=f"(hi) : "l"(v));
}
__device__ __forceinline__ float sum2(ull v) { float lo, hi; upk2(v, lo, hi); return lo + hi; }

__global__ void prep_kernel(const float* __restrict__ w1,
                            const float* __restrict__ wt, const float* __restrict__ wp,
                            const float* __restrict__ wg, const float* __restrict__ wo,
                            const float* __restrict__ w2, const float* __restrict__ w3)
{
    int t = blockIdx.x * blockDim.x + threadIdx.x;
    int n = gridDim.x * blockDim.x;
    for (int i = t; i < 768; i += n) { int c = i / 12, j = i - c * 12;
        g_w1p[i] = (j < 9) ? w1[c * 9 + j] : 0.f; }
    for (int i = t; i < 2048; i += n) { int o = i & 31, c = i >> 5;
        g_qkvT[i]        = wt[o * 64 + c];
        g_qkvT[2048 + i] = wp[o * 64 + c];
        g_qkvT[4096 + i] = wg[o * 64 + c]; }
    for (int i = t; i < 2048; i += n) { int c = i & 63, o = i >> 6;
        g_woT[i] = wo[c * 32 + o]; }
    for (int i = t; i < 20480; i += n) {
        int pair = i / 640, rem = i - pair * 640, co = rem / 20, j = rem - co * 20;
        g_w2p[i] = (j < 18) ? w2[(co * 64 + 2 * pair + (j & 1)) * 9 + (j >> 1)] : 0.f; }
    for (int i = t; i < 2304; i += n) { int o = i & 7, k = (i >> 3) % 9, ci = i / 72;
        g_w3T[i] = w3[(o * 32 + ci) * 9 + k]; }
}

// ---- shared memory layout (float offsets) ----
constexpr int OFF_XIN = 0;            // 121 (pad 128)
constexpr int OFF_W1P = 128;          // 768
constexpr int OFF_B1  = 896;          // 64
constexpr int OFF_BT  = 960;          // 32
constexpr int OFF_BP  = 992;          // 32
constexpr int OFF_BG  = 1024;         // 32
constexpr int OFF_BO  = 1056;         // 64
constexpr int OFF_B2  = 1120;         // 32
constexpr int OFF_B3  = 1152;         // 8 (pad 16)
constexpr int OFF_FB1 = 1168;         // 64
constexpr int OFF_FB2 = 1232;         // 32
constexpr int OFF_FB3 = 1264;         // 16
constexpr int OFF_FB4 = 1280;         // 8
constexpr int OFF_FBO = 1288;         // 2 (pad 4)
constexpr int OFF_A1  = 1292;         // [64][84] conv1 out (residual source)
constexpr int OFF_A2  = 6668;         // [32][49]
constexpr int OFF_A3  = 8236;         // 200 (pad 208)
constexpr int OFF_H1  = 8444;         // 64
constexpr int OFF_H2  = 8508;         // 32
constexpr int OFF_H3  = 8540;         // 16
constexpr int OFF_H4  = 8556;         // 8
constexpr int OFF_U   = 8564;         // 18432-float union region
constexpr int SMEM_FLOATS = OFF_U + 18432;   // 26996 floats = 107984 bytes

// phase A (NLB)
constexpr int UA_QKV = OFF_U;          // 6144 (wtT/wpT/wgT)
constexpr int UA_WO  = OFF_U + 6144;   // 2048
constexpr int UA_TH  = OFF_U + 8192;   // theta [81][32]
constexpr int UA_PH  = OFF_U + 10784;  // phi   [32][81]
constexpr int UA_G   = OFF_U + 13376;  // g     [81][32]
constexpr int UA_YT  = OFF_U;          // yT [32][84] (over dead wtT/wpT-head)
constexpr int UA_PS  = OFF_U + 2688;   // 8 warps x 384 (four softmax rows; over dead wpT/wgT)
// phase B (conv2)
constexpr int UB_A1P = OFF_U + 8192;   // [pair(32)][row(9)][24] = 6912 (over dead TH/PH/G)
constexpr int UB_W2  = OFF_U;          // chunk <=12 pairs x 640 = 7680 (over dead YT/PS/WO)
// phase C
constexpr int UC_W3  = OFF_U;          // 2304
constexpr int UC_FW2 = OFF_U + 2304;   // 2048
constexpr int UC_FW3 = OFF_U + 4352;   // 512
constexpr int UC_FW4 = OFF_U + 4864;   // 128
constexpr int UC_FWO = OFF_U + 4992;   // 16

__global__ __launch_bounds__(256, 2)
void braggnn_kernel(const float* __restrict__ x,
                    const float* __restrict__ b1,
                    const float* __restrict__ bt,  const float* __restrict__ bp,
                    const float* __restrict__ bg,  const float* __restrict__ bo,
                    const float* __restrict__ b2,  const float* __restrict__ b3,
                    const float* __restrict__ fw1, const float* __restrict__ fb1,
                    const float* __restrict__ fw2, const float* __restrict__ fb2,
                    const float* __restrict__ fw3, const float* __restrict__ fb3,
                    const float* __restrict__ fw4, const float* __restrict__ fb4,
                    const float* __restrict__ fwo, const float* __restrict__ fbo,
                    float* __restrict__ out)
{
    extern __shared__ float sm[];
    const int tid  = threadIdx.x;
    const int warp = tid >> 5, lane = tid & 31;
    const int b    = blockIdx.x;

    // ---------------- stage input + phase-A weights (wide) ----------------
    for (int i = tid; i < 121; i += 256) sm[OFF_XIN + i] = x[b * 121 + i];
    if (tid < 192) ((float4*)&sm[OFF_W1P])[tid] = ((const float4*)g_w1p)[tid];
    if (tid < 64) { sm[OFF_B1 + tid] = b1[tid]; sm[OFF_BO + tid] = bo[tid]; sm[OFF_FB1 + tid] = fb1[tid]; }
    if (tid < 32) { sm[OFF_BT + tid] = bt[tid]; sm[OFF_BP + tid] = bp[tid]; sm[OFF_BG + tid] = bg[tid];
                    sm[OFF_B2 + tid] = b2[tid]; sm[OFF_FB2 + tid] = fb2[tid]; }
    if (tid < 16)  sm[OFF_FB3 + tid] = fb3[tid];
    if (tid < 8)  { sm[OFF_B3 + tid] = b3[tid]; sm[OFF_FB4 + tid] = fb4[tid]; }
    if (tid < 2)   sm[OFF_FBO + tid] = fbo[tid];
    for (int i = tid; i < 1536; i += 256) ((float4*)&sm[UA_QKV])[i] = ((const float4*)g_qkvT)[i];
    for (int i = tid; i < 512;  i += 256) ((float4*)&sm[UA_WO])[i]  = ((const float4*)g_woT)[i];
    __syncthreads();

    // ---------------- conv1: [1,11,11] -> [64,9,9] ----------------
    {
        int p = tid & 127;
        if (p < 81) {
            int yy = p / 9, xx = p - yy * 9;
            const float* xr = &sm[OFF_XIN + yy * 11 + xx];
            float x0 = xr[0],  x1 = xr[1],  x2 = xr[2];
            float x3 = xr[11], x4 = xr[12], x5 = xr[13];
            float x6 = xr[22], x7 = xr[23], x8 = xr[24];
            int c0 = (tid >> 7) ? 32 : 0;
            #pragma unroll 8
            for (int c = c0; c < c0 + 32; c++) {
                const float* wr = &sm[OFF_W1P + c * 12];
                float4 wa = *(const float4*)wr;
                float4 wb = *(const float4*)(wr + 4);
                float  w8 = wr[8];
                float acc = sm[OFF_B1 + c];
                acc += wa.x * x0 + wa.y * x1 + wa.z * x2 + wa.w * x3;
                acc += wb.x * x4 + wb.y * x5 + wb.z * x6 + wb.w * x7 + w8 * x8;
                sm[OFF_A1 + c * 84 + p] = acc;
            }
        }
    }
    __syncthreads();

    // ------- theta/phi/g fused projections, 8 positions per task -------
    for (int t = warp; t < 11; t += 8) {
        int s0 = t * 8;
        const float* Wt = &sm[UA_QKV];
        const float* Wp = &sm[UA_QKV + 2048];
        const float* Wg = &sm[UA_QKV + 4096];
        float btv = sm[OFF_BT + lane], bpv = sm[OFF_BP + lane], bgv = sm[OFF_BG + lane];
        ull t01 = pk2(btv, btv), t23 = t01, t45 = t01, t67 = t01;
        ull p01 = pk2(bpv, bpv), p23 = p01, p45 = p01, p67 = p01;
        ull g01 = pk2(bgv, bgv), g23 = g01, g45 = g01, g67 = g01;
        #pragma unroll 4
        for (int c = 0; c < 64; c++) {
            const float* ar = &sm[OFF_A1 + c * 84 + s0];
            float4 av0 = *(const float4*)ar;        // s0..s0+3
            float4 av1 = *(const float4*)(ar + 4);  // s0+4..s0+7 (junk ok for t=10; masked)
            ull a01 = pk2(av0.x, av0.y), a23 = pk2(av0.z, av0.w);
            ull a45 = pk2(av1.x, av1.y), a67 = pk2(av1.z, av1.w);
            float wv = Wt[c * 32 + lane]; ull w = pk2(wv, wv);
            t01 = fma2(w, a01, t01); t23 = fma2(w, a23, t23);
            t45 = fma2(w, a45, t45); t67 = fma2(w, a67, t67);
            wv = Wp[c * 32 + lane]; w = pk2(wv, wv);
            p01 = fma2(w, a01, p01); p23 = fma2(w, a23, p23);
            p45 = fma2(w, a45, p45); p67 = fma2(w, a67, p67);
            wv = Wg[c * 32 + lane]; w = pk2(wv, wv);
            g01 = fma2(w, a01, g01); g23 = fma2(w, a23, g23);
            g45 = fma2(w, a45, g45); g67 = fma2(w, a67, g67);
        }
        int nv = 81 - s0; if (nv > 8) nv = 8;
        float v0, v1, v2x, v3, v4, v5, v6, v7;
        upk2(t01, v0, v1); upk2(t23, v2x, v3); upk2(t45, v4, v5); upk2(t67, v6, v7);
        { float* T = &sm[UA_TH + s0 * 32 + lane];
          T[0] = v0;
          if (nv > 1) T[32]  = v1;  if (nv > 2) T[64]  = v2x; if (nv > 3) T[96]  = v3;
          if (nv > 4) T[128] = v4;  if (nv > 5) T[160] = v5;  if (nv > 6) T[192] = v6;
          if (nv > 7) T[224] = v7; }
        upk2(p01, v0, v1); upk2(p23, v2x, v3); upk2(p45, v4, v5); upk2(p67, v6, v7);
        { float* P = &sm[UA_PH + lane * 81 + s0];
          P[0] = v0;
          if (nv > 1) P[1] = v1;  if (nv > 2) P[2] = v2x; if (nv > 3) P[3] = v3;
          if (nv > 4) P[4] = v4;  if (nv > 5) P[5] = v5;  if (nv > 6) P[6] = v6;
          if (nv > 7) P[7] = v7; }
        upk2(g01, v0, v1); upk2(g23, v2x, v3); upk2(g45, v4, v5); upk2(g67, v6, v7);
        { float* G = &sm[UA_G + s0 * 32 + lane];
          G[0] = v0;
          if (nv > 1) G[32]  = v1;  if (nv > 2) G[64]  = v2x; if (nv > 3) G[96]  = v3;
          if (nv > 4) G[128] = v4;  if (nv > 5) G[160] = v5;  if (nv > 6) G[192] = v6;
          if (nv > 7) G[224] = v7; }
    }
    __syncthreads();

    // ------- attention: 4 rows per iteration share PH / G loads -------
    {
        const float* PH = &sm[UA_PH];
        const float* G  = &sm[UA_G];
        float* PS0 = &sm[UA_PS + warp * 384];
        float* PS1 = PS0 + 96;
        float* PS2 = PS0 + 192;
        float* PS3 = PS0 + 288;
        const bool v2 = (lane < 17);
        #pragma unroll 1
        for (int t = 0; t < 3; t++) {
            int r0 = warp + 32 * t;                 // <= 71, always valid
            int r1 = r0 + 8, r2 = r0 + 16, r3 = r0 + 24;
            bool h1 = (r1 < 81), h2 = (r2 < 81), h3 = (r3 < 81);
            const float* TH0 = &sm[UA_TH + r0 * 32];
            const float* TH1 = &sm[UA_TH + (h1 ? r1 : r0) * 32];
            const float* TH2 = &sm[UA_TH + (h2 ? r2 : r0) * 32];
            const float* TH3 = &sm[UA_TH + (h3 ? r3 : r0) * 32];
            ull s0p = pk2(0.f, 0.f), s1p = s0p, s2p = s0p, s3p = s0p;
            float s0x = 0.f, s1x = 0.f, s2x = 0.f, s3x = 0.f;
            #pragma unroll 4
            for (int i = 0; i < 32; i++) {
                const float* pr = &PH[i * 81 + lane];
                ull pv = pk2(pr[0], pr[32]); float p2 = pr[64];
                float ta = TH0[i], tb = TH1[i], tc = TH2[i], td = TH3[i];
                s0p = fma2(pk2(ta, ta), pv, s0p); s0x += ta * p2;
                s1p = fma2(pk2(tb, tb), pv, s1p); s1x += tb * p2;
                s2p = fma2(pk2(tc, tc), pv, s2p); s2x += tc * p2;
                s3p = fma2(pk2(td, td), pv, s3p); s3x += td * p2;
            }
            float a0, a1, b0, b1, c0, c1, d0, d1;
            upk2(s0p, a0, a1); upk2(s1p, b0, b1); upk2(s2p, c0, c1); upk2(s3p, d0, d1);
            if (!v2) { s0x = -1e30f; s1x = -1e30f; s2x = -1e30f; s3x = -1e30f; }
            float m0 = fmaxf(a0, fmaxf(a1, s0x));
            float m1 = fmaxf(b0, fmaxf(b1, s1x));
            float m2 = fmaxf(c0, fmaxf(c1, s2x));
            float m3 = fmaxf(d0, fmaxf(d1, s3x));
            #pragma unroll
            for (int off = 16; off; off >>= 1) {
                m0 = fmaxf(m0, __shfl_xor_sync(0xffffffffu, m0, off));
                m1 = fmaxf(m1, __shfl_xor_sync(0xffffffffu, m1, off));
                m2 = fmaxf(m2, __shfl_xor_sync(0xffffffffu, m2, off));
                m3 = fmaxf(m3, __shfl_xor_sync(0xffffffffu, m3, off));
            }
            float e00 = __expf(a0 - m0), e01 = __expf(a1 - m0), e02 = v2 ? __expf(s0x - m0) : 0.f;
            float e10 = __expf(b0 - m1), e11 = __expf(b1 - m1), e12 = v2 ? __expf(s1x - m1) : 0.f;
            float e20 = __expf(c0 - m2), e21 = __expf(c1 - m2), e22 = v2 ? __expf(s2x - m2) : 0.f;
            float e30 = __expf(d0 - m3), e31 = __expf(d1 - m3), e32 = v2 ? __expf(s3x - m3) : 0.f;
            float u0 = e00 + e01 + e02, u1 = e10 + e11 + e12;
            float u2 = e20 + e21 + e22, u3 = e30 + e31 + e32;
            #pragma unroll
            for (int off = 16; off; off >>= 1) {
                u0 += __shfl_xor_sync(0xffffffffu, u0, off);
                u1 += __shfl_xor_sync(0xffffffffu, u1, off);
                u2 += __shfl_xor_sync(0xffffffffu, u2, off);
                u3 += __shfl_xor_sync(0xffffffffu, u3, off);
            }
            float i0 = 1.0f / u0, i1 = 1.0f / u1, i2 = 1.0f / u2, i3 = 1.0f / u3;
            PS0[lane] = e00 * i0; PS0[lane + 32] = e01 * i0; if (v2) PS0[lane + 64] = e02 * i0;
            PS1[lane] = e10 * i1; PS1[lane + 32] = e11 * i1; if (v2) PS1[lane + 64] = e12 * i1;
            PS2[lane] = e20 * i2; PS2[lane + 32] = e21 * i2; if (v2) PS2[lane + 64] = e22 * i2;
            PS3[lane] = e30 * i3; PS3[lane + 32] = e31 * i3; if (v2) PS3[lane + 64] = e32 * i3;
            __syncwarp();
            ull y0 = pk2(0.f, 0.f), y1 = y0, y2 = y0, y3 = y0;
            #pragma unroll 5
            for (int t0 = 0; t0 < 80; t0 += 4) {
                const float* gp = &G[t0 * 32 + lane];
                ull gq01 = pk2(gp[0],  gp[32]);
                ull gq23 = pk2(gp[64], gp[96]);
                float4 q0 = *(const float4*)&PS0[t0];
                float4 q1 = *(const float4*)&PS1[t0];
                float4 q2 = *(const float4*)&PS2[t0];
                float4 q3 = *(const float4*)&PS3[t0];
                y0 = fma2(pk2(q0.x, q0.y), gq01, y0); y0 = fma2(pk2(q0.z, q0.w), gq23, y0);
                y1 = fma2(pk2(q1.x, q1.y), gq01, y1); y1 = fma2(pk2(q1.z, q1.w), gq23, y1);
                y2 = fma2(pk2(q2.x, q2.y), gq01, y2); y2 = fma2(pk2(q2.z, q2.w), gq23, y2);
                y3 = fma2(pk2(q3.x, q3.y), gq01, y3); y3 = fma2(pk2(q3.z, q3.w), gq23, y3);
            }
            float gT = G[80 * 32 + lane];
            float* YT = &sm[UA_YT + lane * 84];
            YT[r0] = sum2(y0) + PS0[80] * gT;
            if (h1) YT[r1] = sum2(y1) + PS1[80] * gT;
            if (h2) YT[r2] = sum2(y2) + PS2[80] * gT;
            if (h3) YT[r3] = sum2(y3) + PS3[80] * gT;
            __syncwarp();
        }
    }
    __syncthreads();

    // ---- wo projection + residual + lrelu, written to interleaved A1P ----
    for (int idx = tid; idx < 1344; idx += 256) {      // 64 c * 21 s-groups
        int c = idx & 63, sg = idx >> 6, s0 = sg * 4;
        const float* WO = &sm[UA_WO];
        const float* YT = &sm[UA_YT];
        float bv = sm[OFF_BO + c];
        ull acc01 = pk2(bv, bv), acc23 = pk2(bv, bv);
        #pragma unroll 8
        for (int i = 0; i < 32; i++) {
            float wv = WO[i * 64 + c]; ull w = pk2(wv, wv);
            float4 y4 = *(const float4*)&YT[i * 84 + s0];
            acc01 = fma2(w, pk2(y4.x, y4.y), acc01);
            acc23 = fma2(w, pk2(y4.z, y4.w), acc23);
        }
        float a0, a1v, a2v, a3v;
        upk2(acc01, a0, a1v); upk2(acc23, a2v, a3v);
        int nv = 81 - s0; if (nv > 4) nv = 4;
        const float* A = &sm[OFF_A1 + c * 84 + s0];      // residual source
        float* AP = &sm[UB_A1P + (c >> 1) * 216 + (c & 1)];
        int r = s0 / 9, col = s0 - r * 9;
        AP[r * 24 + col * 2] = lrelu(A[0] + a0);
        col++; if (col == 9) { col = 0; r++; }
        if (nv > 1) { AP[r * 24 + col * 2] = lrelu(A[1] + a1v); col++; if (col == 9) { col = 0; r++; } }
        if (nv > 2) { AP[r * 24 + col * 2] = lrelu(A[2] + a2v); col++; if (col == 9) { col = 0; r++; } }
        if (nv > 3) { AP[r * 24 + col * 2] = lrelu(A[3] + a3v); }
    }
    __syncthreads();

    // ---- conv2: [64,9,9] -> [32,7,7], chunked weight staging, all-wide ----
    ull c2a0, c2a1, c2a2, c2a3, c2a4, c2a5, c2a6;
    if (warp < 7) {
        float bv = sm[OFF_B2 + lane];
        c2a0 = pk2(bv, 0.f); c2a1 = pk2(bv, 0.f); c2a2 = pk2(bv, 0.f);
        c2a3 = pk2(bv, 0.f); c2a4 = pk2(bv, 0.f); c2a5 = pk2(bv, 0.f); c2a6 = pk2(bv, 0.f);
    }
    {
        int pairBase = 0;
        #pragma unroll 1
        for (int gch = 0; gch < 3; gch++) {
            int np = (gch == 0) ? 12 : 10;
            const float4* src = (const float4*)&g_w2p[pairBase * 640];
            float4* dst = (float4*)&sm[UB_W2];
            for (int i = tid; i < np * 160; i += 256) dst[i] = src[i];
            __syncthreads();
            if (warp < 7) {
                const int yy = warp;
                #pragma unroll 1
                for (int lp = 0; lp < np; lp++) {
                    const float* wb = &sm[UB_W2 + lp * 640 + lane * 20];
                    float4 wq0 = *(const float4*)(wb);
                    float4 wq1 = *(const float4*)(wb + 4);
                    float4 wq2 = *(const float4*)(wb + 8);
                    float4 wq3 = *(const float4*)(wb + 12);
                    float2 wq4 = *(const float2*)(wb + 16);
                    ull wk0 = pk2(wq0.x, wq0.y), wk1 = pk2(wq0.z, wq0.w);
                    ull wk2 = pk2(wq1.x, wq1.y), wk3 = pk2(wq1.z, wq1.w);
                    ull wk4 = pk2(wq2.x, wq2.y), wk5 = pk2(wq2.z, wq2.w);
                    ull wk6 = pk2(wq3.x, wq3.y), wk7 = pk2(wq3.z, wq3.w);
                    ull wk8 = pk2(wq4.x, wq4.y);
                    const float* ab = &sm[UB_A1P + (pairBase + lp) * 216];
                    #pragma unroll
                    for (int ky = 0; ky < 3; ky++) {
                        const float* rp = ab + (yy + ky) * 24;
                        float4 q0 = *(const float4*)(rp);
                        float4 q1 = *(const float4*)(rp + 4);
                        float4 q2 = *(const float4*)(rp + 8);
                        float4 q3 = *(const float4*)(rp + 12);
                        float2 q4 = *(const float2*)(rp + 16);
                        ull t0 = pk2(q0.x, q0.y), t1 = pk2(q0.z, q0.w);
                        ull t2 = pk2(q1.x, q1.y), t3 = pk2(q1.z, q1.w);
                        ull t4 = pk2(q2.x, q2.y), t5 = pk2(q2.z, q2.w);
                        ull t6 = pk2(q3.x, q3.y), t7 = pk2(q3.z, q3.w);
                        ull t8 = pk2(q4.x, q4.y);
                        ull wA = (ky == 0) ? wk0 : ((ky == 1) ? wk3 : wk6);
                        ull wB = (ky == 0) ? wk1 : ((ky == 1) ? wk4 : wk7);
                        ull wC = (ky == 0) ? wk2 : ((ky == 1) ? wk5 : wk8);
                        c2a0 = fma2(wA, t0, c2a0); c2a0 = fma2(wB, t1, c2a0); c2a0 = fma2(wC, t2, c2a0);
                        c2a1 = fma2(wA, t1, c2a1); c2a1 = fma2(wB, t2, c2a1); c2a1 = fma2(wC, t3, c2a1);
                        c2a2 = fma2(wA, t2, c2a2); c2a2 = fma2(wB, t3, c2a2); c2a2 = fma2(wC, t4, c2a2);
                        c2a3 = fma2(wA, t3, c2a3); c2a3 = fma2(wB, t4, c2a3); c2a3 = fma2(wC, t5, c2a3);
                        c2a4 = fma2(wA, t4, c2a4); c2a4 = fma2(wB, t5, c2a4); c2a4 = fma2(wC, t6, c2a4);
                        c2a5 = fma2(wA, t5, c2a5); c2a5 = fma2(wB, t6, c2a5); c2a5 = fma2(wC, t7, c2a5);
                        c2a6 = fma2(wA, t6, c2a6); c2a6 = fma2(wB, t7, c2a6); c2a6 = fma2(wC, t8, c2a6);
                    }
                }
            }
            __syncthreads();
            pairBase += np;
        }
    }
    if (warp < 7) {
        float* O = &sm[OFF_A2 + lane * 49 + warp * 7];
        O[0] = lrelu(sum2(c2a0)); O[1] = lrelu(sum2(c2a1)); O[2] = lrelu(sum2(c2a2));
        O[3] = lrelu(sum2(c2a3)); O[4] = lrelu(sum2(c2a4)); O[5] = lrelu(sum2(c2a5));
        O[6] = lrelu(sum2(c2a6));
    }

    // ---------------- stage phase-C weights ----------------
    for (int i = tid; i < 2304; i += 256) sm[UC_W3 + i]  = g_w3T[i];
    for (int i = tid; i < 512;  i += 256) ((float4*)&sm[UC_FW2])[i] = ((const float4*)fw2)[i];
    for (int i = tid; i < 512;  i += 256) sm[UC_FW3 + i] = fw3[i];
    if (tid < 128) sm[UC_FW4 + tid] = fw4[tid];
    if (tid < 16)  sm[UC_FWO + tid] = fwo[tid];
    __syncthreads();

    // ---------------- conv3: [32,7,7] -> [8,5,5] -> flat 200 (packed) ------
    if (tid < 200) {
        int co = tid / 25, p = tid - co * 25, yy = p / 5, xx = p - yy * 5;
        ull acc = pk2(sm[OFF_B3 + co], 0.f);
        #pragma unroll 4
        for (int ci = 0; ci < 32; ci += 2) {
            const float* WL = &sm[UC_W3 + ci * 72 + co];
            const float* WR = WL + 72;
            const float* RL = &sm[OFF_A2 + ci * 49 + yy * 7 + xx];
            const float* RR = RL + 49;
            acc = fma2(pk2(WL[0],  WR[0]),  pk2(RL[0],  RR[0]),  acc);
            acc = fma2(pk2(WL[8],  WR[8]),  pk2(RL[1],  RR[1]),  acc);
            acc = fma2(pk2(WL[16], WR[16]), pk2(RL[2],  RR[2]),  acc);
            acc = fma2(pk2(WL[24], WR[24]), pk2(RL[7],  RR[7]),  acc);
            acc = fma2(pk2(WL[32], WR[32]), pk2(RL[8],  RR[8]),  acc);
            acc = fma2(pk2(WL[40], WR[40]), pk2(RL[9],  RR[9]),  acc);
            acc = fma2(pk2(WL[48], WR[48]), pk2(RL[14], RR[14]), acc);
            acc = fma2(pk2(WL[56], WR[56]), pk2(RL[15], RR[15]), acc);
            acc = fma2(pk2(WL[64], WR[64]), pk2(RL[16], RR[16]), acc);
        }
        sm[OFF_A3 + tid] = lrelu(sum2(acc));
    }
    __syncthreads();

    // ---------------- FC stack (FC1 weights direct from global) ------------
    if (tid < 64) {
        const float4* W = (const float4*)(fw1 + tid * 200);
        float acc = sm[OFF_FB1 + tid];
        #pragma unroll 10
        for (int j = 0; j < 50; j++) {
            float4 w4 = __ldg(W + j);
            float4 a4 = *(const float4*)&sm[OFF_A3 + j * 4];
            acc += w4.x * a4.x + w4.y * a4.y + w4.z * a4.z + w4.w * a4.w;
        }
        sm[OFF_H1 + tid] = lrelu(acc);
    }
    __syncthreads();
    if (tid < 32) {
        const float* W = &sm[UC_FW2 + tid * 64];
        float acc = sm[OFF_FB2 + tid];
        #pragma unroll
        for (int j = 0; j < 64; j += 4) {
            float4 w4 = *(const float4*)&W[j];
            float4 h4 = *(const float4*)&sm[OFF_H1 + j];
            acc += w4.x * h4.x + w4.y * h4.y + w4.z * h4.z + w4.w * h4.w;
        }
        sm[OFF_H2 + tid] = lrelu(acc);
    }
    __syncthreads();
    if (tid < 16) {
        const float* W = &sm[UC_FW3 + tid * 32];
        float acc = sm[OFF_FB3 + tid];
        #pragma unroll
        for (int j = 0; j < 32; j += 4) {
            float4 w4 = *(const float4*)&W[j];
            float4 h4 = *(const float4*)&sm[OFF_H2 + j];
            acc += w4.x * h4.x + w4.y * h4.y + w4.z * h4.z + w4.w * h4.w;
        }
        sm[OFF_H3 + tid] = lrelu(acc);
    }
    __syncthreads();
    if (tid < 8) {
        const float* W = &sm[UC_FW4 + tid * 16];
        float acc = sm[OFF_FB4 + tid];
        #pragma unroll
        for (int j = 0; j < 16; j++) acc += W[j] * sm[OFF_H3 + j];
        sm[OFF_H4 + tid] = lrelu(acc);
    }
    __syncthreads();
    if (tid < 2) {
        const float* W = &sm[UC_FWO + tid * 8];
        float acc = sm[OFF_FBO + tid];
        #pragma unroll
        for (int j = 0; j < 8; j++) acc += W[j] * sm[OFF_H4 + j];
        out[b * 2 + tid] = acc;
    }
}

extern "C" void kernel_launch(void* const* d_in, const int* in_sizes, int n_in,
                              void* d_out, int out_size)
{
    const float* x   = (const float*)d_in[0];
    const float* w1  = (const float*)d_in[1];
    const float* b1  = (const float*)d_in[2];
    const float* wt  = (const float*)d_in[3];
    const float* bt  = (const float*)d_in[4];
    const float* wp  = (const float*)d_in[5];
    const float* bp  = (const float*)d_in[6];
    const float* wg  = (const float*)d_in[7];
    const float* bg  = (const float*)d_in[8];
    const float* wo  = (const float*)d_in[9];
    const float* bo  = (const float*)d_in[10];
    const float* w2  = (const float*)d_in[11];
    const float* b2  = (const float*)d_in[12];
    const float* w3  = (const float*)d_in[13];
    const float* b3  = (const float*)d_in[14];
    const float* fw1 = (const float*)d_in[15];
    const float* fb1 = (const float*)d_in[16];
    const float* fw2 = (const float*)d_in[17];
    const float* fb2 = (const float*)d_in[18];
    const float* fw3 = (const float*)d_in[19];
    const float* fb3 = (const float*)d_in[20];
    const float* fw4 = (const float*)d_in[21];
    const float* fb4 = (const float*)d_in[22];
    const float* fwo = (const float*)d_in[23];
    const float* fbo = (const float*)d_in[24];
    float* out = (float*)d_out;

    const int B = out_size / 2;

    cudaFuncSetAttribute(braggnn_kernel,
                         cudaFuncAttributeMaxDynamicSharedMemorySize,
                         SMEM_FLOATS * (int)sizeof(float));

    prep_kernel<<<24, 256>>>(w1, wt, wp, wg, wo, w2, w3);
    braggnn_kernel<<<B, 256, SMEM_FLOATS * sizeof(float)>>>(
        x, b1, bt, bp, bg, bo, b2, b3,
        fw1, fb1, fw2, fb2, fw3, fb3, fw4, fb4, fwo, fbo, out);
}

// round 17
// speedup vs baseline: 1.4496x; 1.0657x over previous
#include <cuda_runtime.h>

// ---------------------------------------------------------------------------
// BraggNN fused forward.  One sample per block, 256 threads.
// L1/shared-wavefront bound (R14: L1=84.5%, fma=36.0%).
// R15: theta transposed [i][84] + consecutive-row attention quads (1 float4
// broadcast replaces 4 scalar TH broadcasts), float4 YT writes, wo c-pairing.
// ---------------------------------------------------------------------------

#define SLOPE 0.01f
typedef unsigned long long ull;

// pre-transformed weights (device globals: allocation-free)
__device__ float g_w1p [768];    // [c(64)][12]  rows of 9 padded to 12
__device__ float g_qkvT[6144];   // wtT/wpT/wgT : [c(64)][o(32)] each
__device__ float g_woT [2048];   // woT : [i(32)][c(64)]
__device__ float g_w2p [20480];  // [pair(32)][co(32)][20]: j=2k+(ci&1) -> w2[co][2p+(j&1)][k]
__device__ float g_w3T [2304];   // w3T : [ci(32)][k(9)][co(8)]

__device__ __forceinline__ float lrelu(float v) { return v > 0.f ? v : SLOPE * v; }

__device__ __forceinline__ ull pk2(float lo, float hi) {
    ull r; asm("mov.b64 %0, {%1, %2};" : "=l"(r) : "f"(lo), "f"(hi)); return r;
}
__device__ __forceinline__ ull fma2(ull a, ull b, ull c) {
    ull d; asm("fma.rn.f32x2 %0, %1, %2, %3;" : "=l"(d) : "l"(a), "l"(b), "l"(c)); return d;
}
__device__ __forceinline__ void upk2(ull v, float& lo, float& hi) {
    asm("mov.b64 {%0, %1}, %2;" : "=f"(lo), "=f"(hi) : "l"(v));
}
__device__ __forceinline__ float sum2(ull v) { float lo, hi; upk2(v, lo, hi); return lo + hi; }

__global__ void prep_kernel(const float* __restrict__ w1,
                            const float* __restrict__ wt, const float* __restrict__ wp,
                            const float* __restrict__ wg, const float* __restrict__ wo,
                            const float* __restrict__ w2, const float* __restrict__ w3)
{
    int t = blockIdx.x * blockDim.x + threadIdx.x;
    int n = gridDim.x * blockDim.x;
    for (int i = t; i < 768; i += n) { int c = i / 12, j = i - c * 12;
        g_w1p[i] = (j < 9) ? w1[c * 9 + j] : 0.f; }
    for (int i = t; i < 2048; i += n) { int o = i & 31, c = i >> 5;
        g_qkvT[i]        = wt[o * 64 + c];
        g_qkvT[2048 + i] = wp[o * 64 + c];
        g_qkvT[4096 + i] = wg[o * 64 + c]; }
    for (int i = t; i < 2048; i += n) { int c = i & 63, o = i >> 6;
        g_woT[i] = wo[c * 32 + o]; }
    for (int i = t; i < 20480; i += n) {
        int pair = i / 640, rem = i - pair * 640, co = rem / 20, j = rem - co * 20;
        g_w2p[i] = (j < 18) ? w2[(co * 64 + 2 * pair + (j & 1)) * 9 + (j >> 1)] : 0.f; }
    for (int i = t; i < 2304; i += n) { int o = i & 7, k = (i >> 3) % 9, ci = i / 72;
        g_w3T[i] = w3[(o * 32 + ci) * 9 + k]; }
}

// ---- shared memory layout (float offsets) ----
constexpr int OFF_XIN = 0;            // 121 (pad 128)
constexpr int OFF_W1P = 128;          // 768
constexpr int OFF_B1  = 896;          // 64
constexpr int OFF_BT  = 960;          // 32
constexpr int OFF_BP  = 992;          // 32
constexpr int OFF_BG  = 1024;         // 32
constexpr int OFF_BO  = 1056;         // 64
constexpr int OFF_B2  = 1120;         // 32
constexpr int OFF_B3  = 1152;         // 8 (pad 16)
constexpr int OFF_FB1 = 1168;         // 64
constexpr int OFF_FB2 = 1232;         // 32
constexpr int OFF_FB3 = 1264;         // 16
constexpr int OFF_FB4 = 1280;         // 8
constexpr int OFF_FBO = 1288;         // 2 (pad 4)
constexpr int OFF_A1  = 1292;         // [64][84] conv1 out (residual source)
constexpr int OFF_A2  = 6668;         // [32][49]
constexpr int OFF_A3  = 8236;         // 200 (pad 208)
constexpr int OFF_H1  = 8444;         // 64
constexpr int OFF_H2  = 8508;         // 32
constexpr int OFF_H3  = 8540;         // 16
constexpr int OFF_H4  = 8556;         // 8
constexpr int OFF_U   = 8564;         // 18432-float union region
constexpr int SMEM_FLOATS = OFF_U + 18432;   // 26996 floats = 107984 bytes

// phase A (NLB)
constexpr int UA_QKV = OFF_U;          // 6144 (wtT/wpT/wgT)
constexpr int UA_WO  = OFF_U + 6144;   // 2048
constexpr int UA_THt = OFF_U + 8192;   // theta TRANSPOSED [i(32)][84] = 2688
constexpr int UA_PH  = OFF_U + 10880;  // phi   [32][81] = 2592
constexpr int UA_G   = OFF_U + 13472;  // g     [81][32] = 2592 (ends 16064)
constexpr int UA_YT  = OFF_U;          // yT [32][84] (over dead wtT/wpT-head)
constexpr int UA_PS  = OFF_U + 2688;   // 8 warps x 384 (over dead wpT/wgT)
// phase B (conv2)
constexpr int UB_A1P = OFF_U + 8192;   // [pair(32)][row(9)][24] = 6912 (over dead THt/PH/G)
constexpr int UB_W2  = OFF_U;          // chunk <=12 pairs x 640 = 7680 (over dead YT/PS/WO)
// phase C
constexpr int UC_W3  = OFF_U;          // 2304
constexpr int UC_FW2 = OFF_U + 2304;   // 2048
constexpr int UC_FW3 = OFF_U + 4352;   // 512
constexpr int UC_FW4 = OFF_U + 4864;   // 128
constexpr int UC_FWO = OFF_U + 4992;   // 16

__global__ __launch_bounds__(256, 2)
void braggnn_kernel(const float* __restrict__ x,
                    const float* __restrict__ b1,
                    const float* __restrict__ bt,  const float* __restrict__ bp,
                    const float* __restrict__ bg,  const float* __restrict__ bo,
                    const float* __restrict__ b2,  const float* __restrict__ b3,
                    const float* __restrict__ fw1, const float* __restrict__ fb1,
                    const float* __restrict__ fw2, const float* __restrict__ fb2,
                    const float* __restrict__ fw3, const float* __restrict__ fb3,
                    const float* __restrict__ fw4, const float* __restrict__ fb4,
                    const float* __restrict__ fwo, const float* __restrict__ fbo,
                    float* __restrict__ out)
{
    extern __shared__ float sm[];
    const int tid  = threadIdx.x;
    const int warp = tid >> 5, lane = tid & 31;
    const int b    = blockIdx.x;

    // ---------------- stage input + phase-A weights (wide) ----------------
    for (int i = tid; i < 121; i += 256) sm[OFF_XIN + i] = x[b * 121 + i];
    if (tid < 192) ((float4*)&sm[OFF_W1P])[tid] = ((const float4*)g_w1p)[tid];
    if (tid < 64) { sm[OFF_B1 + tid] = b1[tid]; sm[OFF_BO + tid] = bo[tid]; sm[OFF_FB1 + tid] = fb1[tid]; }
    if (tid < 32) { sm[OFF_BT + tid] = bt[tid]; sm[OFF_BP + tid] = bp[tid]; sm[OFF_BG + tid] = bg[tid];
                    sm[OFF_B2 + tid] = b2[tid]; sm[OFF_FB2 + tid] = fb2[tid]; }
    if (tid < 16)  sm[OFF_FB3 + tid] = fb3[tid];
    if (tid < 8)  { sm[OFF_B3 + tid] = b3[tid]; sm[OFF_FB4 + tid] = fb4[tid]; }
    if (tid < 2)   sm[OFF_FBO + tid] = fbo[tid];
    for (int i = tid; i < 1536; i += 256) ((float4*)&sm[UA_QKV])[i] = ((const float4*)g_qkvT)[i];
    for (int i = tid; i < 512;  i += 256) ((float4*)&sm[UA_WO])[i]  = ((const float4*)g_woT)[i];
    __syncthreads();

    // ---------------- conv1: [1,11,11] -> [64,9,9] ----------------
    {
        int p = tid & 127;
        if (p < 81) {
            int yy = p / 9, xx = p - yy * 9;
            const float* xr = &sm[OFF_XIN + yy * 11 + xx];
            float x0 = xr[0],  x1 = xr[1],  x2 = xr[2];
            float x3 = xr[11], x4 = xr[12], x5 = xr[13];
            float x6 = xr[22], x7 = xr[23], x8 = xr[24];
            int c0 = (tid >> 7) ? 32 : 0;
            #pragma unroll 8
            for (int c = c0; c < c0 + 32; c++) {
                const float* wr = &sm[OFF_W1P + c * 12];
                float4 wa = *(const float4*)wr;
                float4 wb = *(const float4*)(wr + 4);
                float  w8 = wr[8];
                float acc = sm[OFF_B1 + c];
                acc += wa.x * x0 + wa.y * x1 + wa.z * x2 + wa.w * x3;
                acc += wb.x * x4 + wb.y * x5 + wb.z * x6 + wb.w * x7 + w8 * x8;
                sm[OFF_A1 + c * 84 + p] = acc;
            }
        }
    }
    __syncthreads();

    // ------- theta/phi/g fused projections, 8 positions per task -------
    // theta now written transposed: THt[o][s]  (lane = o)
    for (int t = warp; t < 11; t += 8) {
        int s0 = t * 8;
        const float* Wt = &sm[UA_QKV];
        const float* Wp = &sm[UA_QKV + 2048];
        const float* Wg = &sm[UA_QKV + 4096];
        float btv = sm[OFF_BT + lane], bpv = sm[OFF_BP + lane], bgv = sm[OFF_BG + lane];
        ull t01 = pk2(btv, btv), t23 = t01, t45 = t01, t67 = t01;
        ull p01 = pk2(bpv, bpv), p23 = p01, p45 = p01, p67 = p01;
        ull g01 = pk2(bgv, bgv), g23 = g01, g45 = g01, g67 = g01;
        #pragma unroll 4
        for (int c = 0; c < 64; c++) {
            const float* ar = &sm[OFF_A1 + c * 84 + s0];
            float4 av0 = *(const float4*)ar;        // s0..s0+3
            float4 av1 = *(const float4*)(ar + 4);  // s0+4..s0+7 (junk ok for t=10; masked)
            ull a01 = pk2(av0.x, av0.y), a23 = pk2(av0.z, av0.w);
            ull a45 = pk2(av1.x, av1.y), a67 = pk2(av1.z, av1.w);
            float wv = Wt[c * 32 + lane]; ull w = pk2(wv, wv);
            t01 = fma2(w, a01, t01); t23 = fma2(w, a23, t23);
            t45 = fma2(w, a45, t45); t67 = fma2(w, a67, t67);
            wv = Wp[c * 32 + lane]; w = pk2(wv, wv);
            p01 = fma2(w, a01, p01); p23 = fma2(w, a23, p23);
            p45 = fma2(w, a45, p45); p67 = fma2(w, a67, p67);
            wv = Wg[c * 32 + lane]; w = pk2(wv, wv);
            g01 = fma2(w, a01, g01); g23 = fma2(w, a23, g23);
            g45 = fma2(w, a45, g45); g67 = fma2(w, a67, g67);
        }
        int nv = 81 - s0; if (nv > 8) nv = 8;
        float v0, v1, v2x, v3, v4, v5, v6, v7;
        // theta transposed: two float4 stores, lane-stride 84 -> conflict-free
        upk2(t01, v0, v1); upk2(t23, v2x, v3); upk2(t45, v4, v5); upk2(t67, v6, v7);
        { float* T = &sm[UA_THt + lane * 84 + s0];
          *(float4*)T = make_float4(v0, v1, v2x, v3);     // t=10: cols 81..83 = padding
          if (nv > 4) *(float4*)(T + 4) = make_float4(v4, v5, v6, v7); }
        upk2(p01, v0, v1); upk2(p23, v2x, v3); upk2(p45, v4, v5); upk2(p67, v6, v7);
        { float* P = &sm[UA_PH + lane * 81 + s0];
          P[0] = v0;
          if (nv > 1) P[1] = v1;  if (nv > 2) P[2] = v2x; if (nv > 3) P[3] = v3;
          if (nv > 4) P[4] = v4;  if (nv > 5) P[5] = v5;  if (nv > 6) P[6] = v6;
          if (nv > 7) P[7] = v7; }
        upk2(g01, v0, v1); upk2(g23, v2x, v3); upk2(g45, v4, v5); upk2(g67, v6, v7);
        { float* G = &sm[UA_G + s0 * 32 + lane];
          G[0] = v0;
          if (nv > 1) G[32]  = v1;  if (nv > 2) G[64]  = v2x; if (nv > 3) G[96]  = v3;
          if (nv > 4) G[128] = v4;  if (nv > 5) G[160] = v5;  if (nv > 6) G[192] = v6;
          if (nv > 7) G[224] = v7; }
    }
    __syncthreads();

    // ------- attention: CONSECUTIVE 4-row quads; one float4 TH broadcast --
    {
        const float* PH = &sm[UA_PH];
        const float* G  = &sm[UA_G];
        float* PS0 = &sm[UA_PS + warp * 384];
        float* PS1 = PS0 + 96;
        float* PS2 = PS0 + 192;
        float* PS3 = PS0 + 288;
        const bool v2 = (lane < 17);
        #pragma unroll 1
        for (int t = 0; t < 3; t++) {
            int r0 = 4 * warp + 32 * t;             // quads 0,4,...,92
            if (r0 > 80) continue;                  // uniform per warp
            bool h1 = (r0 + 1 < 81), h2 = (r0 + 2 < 81), h3 = (r0 + 3 < 81);
            ull s0p = pk2(0.f, 0.f), s1p = s0p, s2p = s0p, s3p = s0p;
            float s0x = 0.f, s1x = 0.f, s2x = 0.f, s3x = 0.f;
            #pragma unroll 4
            for (int i = 0; i < 32; i++) {
                const float* pr = &PH[i * 81 + lane];
                ull pv = pk2(pr[0], pr[32]); float p2 = pr[64];
                float4 th4 = *(const float4*)&sm[UA_THt + i * 84 + r0];  // 1 broadcast
                s0p = fma2(pk2(th4.x, th4.x), pv, s0p); s0x += th4.x * p2;
                s1p = fma2(pk2(th4.y, th4.y), pv, s1p); s1x += th4.y * p2;
                s2p = fma2(pk2(th4.z, th4.z), pv, s2p); s2x += th4.z * p2;
                s3p = fma2(pk2(th4.w, th4.w), pv, s3p); s3x += th4.w * p2;
            }
            float a0, a1, b0, b1, c0, c1, d0, d1;
            upk2(s0p, a0, a1); upk2(s1p, b0, b1); upk2(s2p, c0, c1); upk2(s3p, d0, d1);
            if (!v2) { s0x = -1e30f; s1x = -1e30f; s2x = -1e30f; s3x = -1e30f; }
            float m0 = fmaxf(a0, fmaxf(a1, s0x));
            float m1 = fmaxf(b0, fmaxf(b1, s1x));
            float m2 = fmaxf(c0, fmaxf(c1, s2x));
            float m3 = fmaxf(d0, fmaxf(d1, s3x));
            #pragma unroll
            for (int off = 16; off; off >>= 1) {
                m0 = fmaxf(m0, __shfl_xor_sync(0xffffffffu, m0, off));
                m1 = fmaxf(m1, __shfl_xor_sync(0xffffffffu, m1, off));
                m2 = fmaxf(m2, __shfl_xor_sync(0xffffffffu, m2, off));
                m3 = fmaxf(m3, __shfl_xor_sync(0xffffffffu, m3, off));
            }
            float e00 = __expf(a0 - m0), e01 = __expf(a1 - m0), e02 = v2 ? __expf(s0x - m0) : 0.f;
            float e10 = __expf(b0 - m1), e11 = __expf(b1 - m1), e12 = v2 ? __expf(s1x - m1) : 0.f;
            float e20 = __expf(c0 - m2), e21 = __expf(c1 - m2), e22 = v2 ? __expf(s2x - m2) : 0.f;
            float e30 = __expf(d0 - m3), e31 = __expf(d1 - m3), e32 = v2 ? __expf(s3x - m3) : 0.f;
            float u0 = e00 + e01 + e02, u1 = e10 + e11 + e12;
            float u2 = e20 + e21 + e22, u3 = e30 + e31 + e32;
            #pragma unroll
            for (int off = 16; off; off >>= 1) {
                u0 += __shfl_xor_sync(0xffffffffu, u0, off);
                u1 += __shfl_xor_sync(0xffffffffu, u1, off);
                u2 += __shfl_xor_sync(0xffffffffu, u2, off);
                u3 += __shfl_xor_sync(0xffffffffu, u3, off);
            }
            float i0 = 1.0f / u0, i1 = 1.0f / u1, i2 = 1.0f / u2, i3 = 1.0f / u3;
            PS0[lane] = e00 * i0; PS0[lane + 32] = e01 * i0; if (v2) PS0[lane + 64] = e02 * i0;
            PS1[lane] = e10 * i1; PS1[lane + 32] = e11 * i1; if (v2) PS1[lane + 64] = e12 * i1;
            PS2[lane] = e20 * i2; PS2[lane + 32] = e21 * i2; if (v2) PS2[lane + 64] = e22 * i2;
            PS3[lane] = e30 * i3; PS3[lane + 32] = e31 * i3; if (v2) PS3[lane + 64] = e32 * i3;
            __syncwarp();
            ull y0 = pk2(0.f, 0.f), y1 = y0, y2 = y0, y3 = y0;
            #pragma unroll 5
            for (int t0 = 0; t0 < 80; t0 += 4) {
                const float* gp = &G[t0 * 32 + lane];
                ull gq01 = pk2(gp[0],  gp[32]);
                ull gq23 = pk2(gp[64], gp[96]);
                float4 q0 = *(const float4*)&PS0[t0];
                float4 q1 = *(const float4*)&PS1[t0];
                float4 q2 = *(const float4*)&PS2[t0];
                float4 q3 = *(const float4*)&PS3[t0];
                y0 = fma2(pk2(q0.x, q0.y), gq01, y0); y0 = fma2(pk2(q0.z, q0.w), gq23, y0);
                y1 = fma2(pk2(q1.x, q1.y), gq01, y1); y1 = fma2(pk2(q1.z, q1.w), gq23, y1);
                y2 = fma2(pk2(q2.x, q2.y), gq01, y2); y2 = fma2(pk2(q2.z, q2.w), gq23, y2);
                y3 = fma2(pk2(q3.x, q3.y), gq01, y3); y3 = fma2(pk2(q3.z, q3.w), gq23, y3);
            }
            float gT = G[80 * 32 + lane];
            float yv0 = sum2(y0) + PS0[80] * gT;
            float yv1 = sum2(y1) + PS1[80] * gT;
            float yv2 = sum2(y2) + PS2[80] * gT;
            float yv3 = sum2(y3) + PS3[80] * gT;
            float* YTp = &sm[UA_YT + lane * 84];
            if (h3) {                               // full quad: one float4 store
                *(float4*)&YTp[r0] = make_float4(yv0, yv1, yv2, yv3);
            } else {                                // r0 == 80 edge
                YTp[r0] = yv0;
                if (h1) YTp[r0 + 1] = yv1;
                if (h2) YTp[r0 + 2] = yv2;
            }
            __syncwarp();
        }
    }
    __syncthreads();

    // ---- wo projection (c and c+32 paired) + residual + lrelu -> A1P ----
    for (int idx = tid; idx < 672; idx += 256) {       // 32 c-pairs * 21 s-groups
        int c0 = idx & 31, sg = idx >> 5, s0 = sg * 4;
        int c1 = c0 + 32;
        const float* WO = &sm[UA_WO];
        const float* YT = &sm[UA_YT];
        float bv0 = sm[OFF_BO + c0], bv1 = sm[OFF_BO + c1];
        ull a0_01 = pk2(bv0, bv0), a0_23 = pk2(bv0, bv0);
        ull a1_01 = pk2(bv1, bv1), a1_23 = pk2(bv1, bv1);
        #pragma unroll 8
        for (int i = 0; i < 32; i++) {
            float4 y4 = *(const float4*)&YT[i * 84 + s0];   // broadcast, shared by both c
            ull yA = pk2(y4.x, y4.y), yB = pk2(y4.z, y4.w);
            float wv0 = WO[i * 64 + c0]; ull w0 = pk2(wv0, wv0);
            float wv1 = WO[i * 64 + c1]; ull w1 = pk2(wv1, wv1);
            a0_01 = fma2(w0, yA, a0_01); a0_23 = fma2(w0, yB, a0_23);
            a1_01 = fma2(w1, yA, a1_01); a1_23 = fma2(w1, yB, a1_23);
        }
        int nv = 81 - s0; if (nv > 4) nv = 4;
        // channel c0
        {
            float q0, q1, q2, q3;
            upk2(a0_01, q0, q1); upk2(a0_23, q2, q3);
            const float* A = &sm[OFF_A1 + c0 * 84 + s0];
            float* AP = &sm[UB_A1P + (c0 >> 1) * 216 + (c0 & 1)];
            int r = s0 / 9, col = s0 - r * 9;
            AP[r * 24 + col * 2] = lrelu(A[0] + q0);
            col++; if (col == 9) { col = 0; r++; }
            if (nv > 1) { AP[r * 24 + col * 2] = lrelu(A[1] + q1); col++; if (col == 9) { col = 0; r++; } }
            if (nv > 2) { AP[r * 24 + col * 2] = lrelu(A[2] + q2); col++; if (col == 9) { col = 0; r++; } }
            if (nv > 3) { AP[r * 24 + col * 2] = lrelu(A[3] + q3); }
        }
        // channel c1
        {
            float q0, q1, q2, q3;
            upk2(a1_01, q0, q1); upk2(a1_23, q2, q3);
            const float* A = &sm[OFF_A1 + c1 * 84 + s0];
            float* AP = &sm[UB_A1P + (c1 >> 1) * 216 + (c1 & 1)];
            int r = s0 / 9, col = s0 - r * 9;
            AP[r * 24 + col * 2] = lrelu(A[0] + q0);
            col++; if (col == 9) { col = 0; r++; }
            if (nv > 1) { AP[r * 24 + col * 2] = lrelu(A[1] + q1); col++; if (col == 9) { col = 0; r++; } }
            if (nv > 2) { AP[r * 24 + col * 2] = lrelu(A[2] + q2); col++; if (col == 9) { col = 0; r++; } }
            if (nv > 3) { AP[r * 24 + col * 2] = lrelu(A[3] + q3); }
        }
    }
    __syncthreads();

    // ---- conv2: [64,9,9] -> [32,7,7], chunked weight staging, all-wide ----
    ull c2a0, c2a1, c2a2, c2a3, c2a4, c2a5, c2a6;
    if (warp < 7) {
        float bv = sm[OFF_B2 + lane];
        c2a0 = pk2(bv, 0.f); c2a1 = pk2(bv, 0.f); c2a2 = pk2(bv, 0.f);
        c2a3 = pk2(bv, 0.f); c2a4 = pk2(bv, 0.f); c2a5 = pk2(bv, 0.f); c2a6 = pk2(bv, 0.f);
    }
    {
        int pairBase = 0;
        #pragma unroll 1
        for (int gch = 0; gch < 3; gch++) {
            int np = (gch == 0) ? 12 : 10;
            const float4* src = (const float4*)&g_w2p[pairBase * 640];
            float4* dst = (float4*)&sm[UB_W2];
            for (int i = tid; i < np * 160; i += 256) dst[i] = src[i];
            __syncthreads();
            if (warp < 7) {
                const int yy = warp;
                #pragma unroll 1
                for (int lp = 0; lp < np; lp++) {
                    const float* wb = &sm[UB_W2 + lp * 640 + lane * 20];
                    float4 wq0 = *(const float4*)(wb);
                    float4 wq1 = *(const float4*)(wb + 4);
                    float4 wq2 = *(const float4*)(wb + 8);
                    float4 wq3 = *(const float4*)(wb + 12);
                    float2 wq4 = *(const float2*)(wb + 16);
                    ull wk0 = pk2(wq0.x, wq0.y), wk1 = pk2(wq0.z, wq0.w);
                    ull wk2 = pk2(wq1.x, wq1.y), wk3 = pk2(wq1.z, wq1.w);
                    ull wk4 = pk2(wq2.x, wq2.y), wk5 = pk2(wq2.z, wq2.w);
                    ull wk6 = pk2(wq3.x, wq3.y), wk7 = pk2(wq3.z, wq3.w);
                    ull wk8 = pk2(wq4.x, wq4.y);
                    const float* ab = &sm[UB_A1P + (pairBase + lp) * 216];
                    #pragma unroll
                    for (int ky = 0; ky < 3; ky++) {
                        const float* rp = ab + (yy + ky) * 24;
                        float4 q0 = *(const float4*)(rp);
                        float4 q1 = *(const float4*)(rp + 4);
                        float4 q2 = *(const float4*)(rp + 8);
                        float4 q3 = *(const float4*)(rp + 12);
                        float2 q4 = *(const float2*)(rp + 16);
                        ull t0 = pk2(q0.x, q0.y), t1 = pk2(q0.z, q0.w);
                        ull t2 = pk2(q1.x, q1.y), t3 = pk2(q1.z, q1.w);
                        ull t4 = pk2(q2.x, q2.y), t5 = pk2(q2.z, q2.w);
                        ull t6 = pk2(q3.x, q3.y), t7 = pk2(q3.z, q3.w);
                        ull t8 = pk2(q4.x, q4.y);
                        ull wA = (ky == 0) ? wk0 : ((ky == 1) ? wk3 : wk6);
                        ull wB = (ky == 0) ? wk1 : ((ky == 1) ? wk4 : wk7);
                        ull wC = (ky == 0) ? wk2 : ((ky == 1) ? wk5 : wk8);
                        c2a0 = fma2(wA, t0, c2a0); c2a0 = fma2(wB, t1, c2a0); c2a0 = fma2(wC, t2, c2a0);
                        c2a1 = fma2(wA, t1, c2a1); c2a1 = fma2(wB, t2, c2a1); c2a1 = fma2(wC, t3, c2a1);
                        c2a2 = fma2(wA, t2, c2a2); c2a2 = fma2(wB, t3, c2a2); c2a2 = fma2(wC, t4, c2a2);
                        c2a3 = fma2(wA, t3, c2a3); c2a3 = fma2(wB, t4, c2a3); c2a3 = fma2(wC, t5, c2a3);
                        c2a4 = fma2(wA, t4, c2a4); c2a4 = fma2(wB, t5, c2a4); c2a4 = fma2(wC, t6, c2a4);
                        c2a5 = fma2(wA, t5, c2a5); c2a5 = fma2(wB, t6, c2a5); c2a5 = fma2(wC, t7, c2a5);
                        c2a6 = fma2(wA, t6, c2a6); c2a6 = fma2(wB, t7, c2a6); c2a6 = fma2(wC, t8, c2a6);
                    }
                }
            }
            __syncthreads();
            pairBase += np;
        }
    }
    if (warp < 7) {
        float* O = &sm[OFF_A2 + lane * 49 + warp * 7];
        O[0] = lrelu(sum2(c2a0)); O[1] = lrelu(sum2(c2a1)); O[2] = lrelu(sum2(c2a2));
        O[3] = lrelu(sum2(c2a3)); O[4] = lrelu(sum2(c2a4)); O[5] = lrelu(sum2(c2a5));
        O[6] = lrelu(sum2(c2a6));
    }

    // ---------------- stage phase-C weights ----------------
    for (int i = tid; i < 2304; i += 256) sm[UC_W3 + i]  = g_w3T[i];
    for (int i = tid; i < 512;  i += 256) ((float4*)&sm[UC_FW2])[i] = ((const float4*)fw2)[i];
    for (int i = tid; i < 512;  i += 256) sm[UC_FW3 + i] = fw3[i];
    if (tid < 128) sm[UC_FW4 + tid] = fw4[tid];
    if (tid < 16)  sm[UC_FWO + tid] = fwo[tid];
    __syncthreads();

    // ---------------- conv3: [32,7,7] -> [8,5,5] -> flat 200 (packed) ------
    if (tid < 200) {
        int co = tid / 25, p = tid - co * 25, yy = p / 5, xx = p - yy * 5;
        ull acc = pk2(sm[OFF_B3 + co], 0.f);
        #pragma unroll 4
        for (int ci = 0; ci < 32; ci += 2) {
            const float* WL = &sm[UC_W3 + ci * 72 + co];
            const float* WR = WL + 72;
            const float* RL = &sm[OFF_A2 + ci * 49 + yy * 7 + xx];
            const float* RR = RL + 49;
            acc = fma2(pk2(WL[0],  WR[0]),  pk2(RL[0],  RR[0]),  acc);
            acc = fma2(pk2(WL[8],  WR[8]),  pk2(RL[1],  RR[1]),  acc);
            acc = fma2(pk2(WL[16], WR[16]), pk2(RL[2],  RR[2]),  acc);
            acc = fma2(pk2(WL[24], WR[24]), pk2(RL[7],  RR[7]),  acc);
            acc = fma2(pk2(WL[32], WR[32]), pk2(RL[8],  RR[8]),  acc);
            acc = fma2(pk2(WL[40], WR[40]), pk2(RL[9],  RR[9]),  acc);
            acc = fma2(pk2(WL[48], WR[48]), pk2(RL[14], RR[14]), acc);
            acc = fma2(pk2(WL[56], WR[56]), pk2(RL[15], RR[15]), acc);
            acc = fma2(pk2(WL[64], WR[64]), pk2(RL[16], RR[16]), acc);
        }
        sm[OFF_A3 + tid] = lrelu(sum2(acc));
    }
    __syncthreads();

    // ---------------- FC stack (FC1 weights direct from global) ------------
    if (tid < 64) {
        const float4* W = (const float4*)(fw1 + tid * 200);
        float acc = sm[OFF_FB1 + tid];
        #pragma unroll 10
        for (int j = 0; j < 50; j++) {
            float4 w4 = __ldg(W + j);
            float4 a4 = *(const float4*)&sm[OFF_A3 + j * 4];
            acc += w4.x * a4.x + w4.y * a4.y + w4.z * a4.z + w4.w * a4.w;
        }
        sm[OFF_H1 + tid] = lrelu(acc);
    }
    __syncthreads();
    if (tid < 32) {
        const float* W = &sm[UC_FW2 + tid * 64];
        float acc = sm[OFF_FB2 + tid];
        #pragma unroll
        for (int j = 0; j < 64; j += 4) {
            float4 w4 = *(const float4*)&W[j];
            float4 h4 = *(const float4*)&sm[OFF_H1 + j];
            acc += w4.x * h4.x + w4.y * h4.y + w4.z * h4.z + w4.w * h4.w;
        }
        sm[OFF_H2 + tid] = lrelu(acc);
    }
    __syncthreads();
    if (tid < 16) {
        const float* W = &sm[UC_FW3 + tid * 32];
        float acc = sm[OFF_FB3 + tid];
        #pragma unroll
        for (int j = 0; j < 32; j += 4) {
            float4 w4 = *(const float4*)&W[j];
            float4 h4 = *(const float4*)&sm[OFF_H2 + j];
            acc += w4.x * h4.x + w4.y * h4.y + w4.z * h4.z + w4.w * h4.w;
        }
        sm[OFF_H3 + tid] = lrelu(acc);
    }
    __syncthreads();
    if (tid < 8) {
        const float* W = &sm[UC_FW4 + tid * 16];
        float acc = sm[OFF_FB4 + tid];
        #pragma unroll
        for (int j = 0; j < 16; j++) acc += W[j] * sm[OFF_H3 + j];
        sm[OFF_H4 + tid] = lrelu(acc);
    }
    __syncthreads();
    if (tid < 2) {
        const float* W = &sm[UC_FWO + tid * 8];
        float acc = sm[OFF_FBO + tid];
        #pragma unroll
        for (int j = 0; j < 8; j++) acc += W[j] * sm[OFF_H4 + j];
        out[b * 2 + tid] = acc;
    }
}

extern "C" void kernel_launch(void* const* d_in, const int* in_sizes, int n_in,
                              void* d_out, int out_size)
{
    const float* x   = (const float*)d_in[0];
    const float* w1  = (const float*)d_in[1];
    const float* b1  = (const float*)d_in[2];
    const float* wt  = (const float*)d_in[3];
    const float* bt  = (const float*)d_in[4];
    const float* wp  = (const float*)d_in[5];
    const float* bp  = (const float*)d_in[6];
    const float* wg  = (const float*)d_in[7];
    const float* bg  = (const float*)d_in[8];
    const float* wo  = (const float*)d_in[9];
    const float* bo  = (const float*)d_in[10];
    const float* w2  = (const float*)d_in[11];
    const float* b2  = (const float*)d_in[12];
    const float* w3  = (const float*)d_in[13];
    const float* b3  = (const float*)d_in[14];
    const float* fw1 = (const float*)d_in[15];
    const float* fb1 = (const float*)d_in[16];
    const float* fw2 = (const float*)d_in[17];
    const float* fb2 = (const float*)d_in[18];
    const float* fw3 = (const float*)d_in[19];
    const float* fb3 = (const float*)d_in[20];
    const float* fw4 = (const float*)d_in[21];
    const float* fb4 = (const float*)d_in[22];
    const float* fwo = (const float*)d_in[23];
    const float* fbo = (const float*)d_in[24];
    float* out = (float*)d_out;

    const int B = out_size / 2;

    cudaFuncSetAttribute(braggnn_kernel,
                         cudaFuncAttributeMaxDynamicSharedMemorySize,
                         SMEM_FLOATS * (int)sizeof(float));

    prep_kernel<<<24, 256>>>(w1, wt, wp, wg, wo, w2, w3);
    braggnn_kernel<<<B, 256, SMEM_FLOATS * sizeof(float)>>>(
        x, b1, bt, bp, bg, bo, b2, b3,
        fw1, fb1, fw2, fb2, fw3, fb3, fw4, fb4, fwo, fbo, out);
}